// round 5
// baseline (speedup 1.0000x reference)
#include <cuda_runtime.h>
#include <cstdint>
#include <cmath>

// Problem constants (match reference_code)
#define NN     50000
#define EE     800000
#define ETOT   (NN + EE)
#define IND    256
#define HIDD   64
#define NHEADS 4
#define D1     256    // heads*hid layer 1 output width
#define D2     64     // layer 2 output width
#define NEG_SLOPE 0.2f

// ---------------------------------------------------------------------------
// Scratch (no allocations allowed -> __device__ globals)
// ---------------------------------------------------------------------------
__device__ __align__(16) float g_h1[(size_t)NN * D1];   // x @ W1
__device__ __align__(16) float g_hr[(size_t)NN * D1];   // relu(agg1 + b1)
__device__ __align__(16) float g_h2[(size_t)NN * D2];   // hr @ W2
__device__ __align__(16) float g_as1[NN * NHEADS];
__device__ __align__(16) float g_ad1[NN * NHEADS];
__device__ __align__(16) float g_as2[NN];
__device__ __align__(16) float g_ad2[NN];
__device__ int   g_deg[NN];
__device__ int   g_row[NN + 1];
__device__ int   g_cur[NN];
__device__ int   g_csr[ETOT];             // src node per (dst-sorted) edge

// ---------------------------------------------------------------------------
// Tiled SGEMM: C[M,N] = A[M,K] @ B[K,N]   (fp32, BM=BN=64, BK=16, 4x4/thread)
// ---------------------------------------------------------------------------
#define BM 64
#define BN 64
#define BK 16
#define TM 4
#define TN 4

template <int LAYER>
__global__ void __launch_bounds__(256)
sgemm_kernel(const float* __restrict__ Aext,
             const float* __restrict__ B,
             int M, int N, int K)
{
    const float* __restrict__ A = (LAYER == 1) ? Aext : g_hr;
    float* __restrict__ C       = (LAYER == 1) ? g_h1 : g_h2;

    __shared__ __align__(16) float As[BK][BM];
    __shared__ __align__(16) float Bs[BK][BN];

    const int tid = threadIdx.x;                 // 256 threads
    const int block_row = blockIdx.y * BM;
    const int block_col = blockIdx.x * BN;

    const int trow = (tid / (BN / TN)) * TM;     // 0..60 step 4
    const int tcol = (tid % (BN / TN)) * TN;     // 0..60 step 4

    // A tile loader: 64x16, one float4 per thread
    const int a_row = tid / 4;
    const int a_col = (tid % 4) * 4;
    // B tile loader: 16x64, one float4 per thread
    const int b_row = tid / 16;
    const int b_col = (tid % 16) * 4;

    float acc[TM][TN];
#pragma unroll
    for (int i = 0; i < TM; i++)
#pragma unroll
        for (int j = 0; j < TN; j++) acc[i][j] = 0.f;

    for (int k0 = 0; k0 < K; k0 += BK) {
        float4 av = make_float4(0.f, 0.f, 0.f, 0.f);
        const int gr = block_row + a_row;
        if (gr < M)
            av = *reinterpret_cast<const float4*>(A + (size_t)gr * K + k0 + a_col);
        As[a_col + 0][a_row] = av.x;
        As[a_col + 1][a_row] = av.y;
        As[a_col + 2][a_row] = av.z;
        As[a_col + 3][a_row] = av.w;

        const float4 bv = *reinterpret_cast<const float4*>(
            B + (size_t)(k0 + b_row) * N + block_col + b_col);
        *reinterpret_cast<float4*>(&Bs[b_row][b_col]) = bv;

        __syncthreads();

#pragma unroll
        for (int k = 0; k < BK; k++) {
            const float4 ar = *reinterpret_cast<const float4*>(&As[k][trow]);
            const float4 br = *reinterpret_cast<const float4*>(&Bs[k][tcol]);
            const float arr[TM] = {ar.x, ar.y, ar.z, ar.w};
            const float brr[TN] = {br.x, br.y, br.z, br.w};
#pragma unroll
            for (int i = 0; i < TM; i++)
#pragma unroll
                for (int j = 0; j < TN; j++)
                    acc[i][j] += arr[i] * brr[j];
        }
        __syncthreads();
    }

#pragma unroll
    for (int i = 0; i < TM; i++) {
        const int gr = block_row + trow + i;
        if (gr < M) {
            float4 v = make_float4(acc[i][0], acc[i][1], acc[i][2], acc[i][3]);
            *reinterpret_cast<float4*>(C + (size_t)gr * N + block_col + tcol) = v;
        }
    }
}

// ---------------------------------------------------------------------------
// Attention logit dot products
// ---------------------------------------------------------------------------
__global__ void alpha1_kernel(const float* __restrict__ a_src,
                              const float* __restrict__ a_dst, int n)
{
    const int i = blockIdx.x * blockDim.x + threadIdx.x;
    if (i >= n) return;
    const float4* row = reinterpret_cast<const float4*>(g_h1 + (size_t)i * D1);
    const float4* asv = reinterpret_cast<const float4*>(a_src);
    const float4* adv = reinterpret_cast<const float4*>(a_dst);
    float s[NHEADS] = {0.f, 0.f, 0.f, 0.f};
    float d[NHEADS] = {0.f, 0.f, 0.f, 0.f};
#pragma unroll
    for (int q = 0; q < D1 / 4; q++) {
        const float4 v = row[q];
        const float4 a = asv[q];
        const float4 b = adv[q];
        const int h = q >> 4;   // q*4/64
        s[h] += v.x * a.x + v.y * a.y + v.z * a.z + v.w * a.w;
        d[h] += v.x * b.x + v.y * b.y + v.z * b.z + v.w * b.w;
    }
#pragma unroll
    for (int h = 0; h < NHEADS; h++) {
        g_as1[i * NHEADS + h] = s[h];
        g_ad1[i * NHEADS + h] = d[h];
    }
}

__global__ void alpha2_kernel(const float* __restrict__ a_src,
                              const float* __restrict__ a_dst, int n)
{
    const int i = blockIdx.x * blockDim.x + threadIdx.x;
    if (i >= n) return;
    const float4* row = reinterpret_cast<const float4*>(g_h2 + (size_t)i * D2);
    const float4* asv = reinterpret_cast<const float4*>(a_src);
    const float4* adv = reinterpret_cast<const float4*>(a_dst);
    float s = 0.f, d = 0.f;
#pragma unroll
    for (int q = 0; q < D2 / 4; q++) {
        const float4 v = row[q];
        const float4 a = asv[q];
        const float4 b = adv[q];
        s += v.x * a.x + v.y * a.y + v.z * a.z + v.w * a.w;
        d += v.x * b.x + v.y * b.y + v.z * b.z + v.w * b.w;
    }
    g_as2[i] = s;
    g_ad2[i] = d;
}

// ---------------------------------------------------------------------------
// CSR build: histogram -> exclusive scan -> scatter
// edge_index is INT32 (JAX silently downcasts int64 without x64 mode):
//   ei[0..E)   = src node ids, ei[E..2E) = dst node ids.
// Unsigned bounds guards: never trap on unexpected data.
// ---------------------------------------------------------------------------
__global__ void zero_deg_kernel(int n)
{
    const int i = blockIdx.x * blockDim.x + threadIdx.x;
    if (i < n) g_deg[i] = 0;
}

__global__ void hist_kernel(const int* __restrict__ ei, int E, int n)
{
    const int i = blockIdx.x * blockDim.x + threadIdx.x;
    const int tot = E + n;
    if (i >= tot) return;
    const int d = (i < E) ? ei[E + i] : (i - E);
    if ((unsigned)d < (unsigned)n)
        atomicAdd(&g_deg[d], 1);
}

__global__ void scan_kernel(int n)
{
    __shared__ int smem[1024];
    __shared__ int carry;
    const int tid = threadIdx.x;
    if (tid == 0) carry = 0;
    __syncthreads();
    for (int base = 0; base < n; base += 1024) {
        const int i = base + tid;
        const int v = (i < n) ? g_deg[i] : 0;
        int x = v;
#pragma unroll
        for (int off = 1; off < 1024; off <<= 1) {
            smem[tid] = x;
            __syncthreads();
            if (tid >= off) x += smem[tid - off];
            __syncthreads();
        }
        const int excl = x - v + carry;
        if (i < n) {
            g_row[i] = excl;
            g_cur[i] = excl;
        }
        __syncthreads();
        if (tid == 1023) carry += x;   // x of last thread = chunk total
        __syncthreads();
    }
    if (tid == 0) g_row[n] = carry;
}

__global__ void scatter_kernel(const int* __restrict__ ei, int E, int n)
{
    const int i = blockIdx.x * blockDim.x + threadIdx.x;
    const int tot = E + n;
    if (i >= tot) return;
    int s, d;
    if (i < E) {
        s = ei[i];
        d = ei[E + i];
    } else {
        s = d = i - E;
    }
    if ((unsigned)d < (unsigned)n && (unsigned)s < (unsigned)n) {
        const int pos = atomicAdd(&g_cur[d], 1);
        if ((unsigned)pos < (unsigned)ETOT)
            g_csr[pos] = s;
    }
}

// ---------------------------------------------------------------------------
// GAT aggregation, warp-per-destination (3-pass softmax, chunked gather).
// ---------------------------------------------------------------------------
#define AGG_WARPS 8

template <int HEADS, int RP, bool L1>
__global__ void __launch_bounds__(AGG_WARPS * 32)
agg_kernel(const float* __restrict__ bias,
           float* __restrict__ out_ext, int n)
{
    constexpr int D = RP * 32;
    const float* __restrict__ h  = L1 ? g_h1  : g_h2;
    const float* __restrict__ as = L1 ? g_as1 : g_as2;
    const float* __restrict__ ad = L1 ? g_ad1 : g_ad2;
    float* __restrict__ out      = L1 ? g_hr  : out_ext;

    __shared__ int   s_src[AGG_WARPS][32];
    __shared__ float s_w[AGG_WARPS][32][HEADS];

    const int warp  = (blockIdx.x * blockDim.x + threadIdx.x) >> 5;
    const int wslot = threadIdx.x >> 5;
    const int lane  = threadIdx.x & 31;
    if (warp >= n) return;

    const int start = g_row[warp];
    const int end   = g_row[warp + 1];

    float adv[HEADS];
#pragma unroll
    for (int hh = 0; hh < HEADS; hh++) adv[hh] = ad[warp * HEADS + hh];

    // ---- pass 1: max ----
    float m[HEADS];
#pragma unroll
    for (int hh = 0; hh < HEADS; hh++) m[hh] = -1e30f;
    for (int i = start + lane; i < end; i += 32) {
        const int s = g_csr[i];
#pragma unroll
        for (int hh = 0; hh < HEADS; hh++) {
            float e = as[s * HEADS + hh] + adv[hh];
            e = (e >= 0.f) ? e : NEG_SLOPE * e;
            m[hh] = fmaxf(m[hh], e);
        }
    }
#pragma unroll
    for (int hh = 0; hh < HEADS; hh++) {
#pragma unroll
        for (int off = 16; off > 0; off >>= 1)
            m[hh] = fmaxf(m[hh], __shfl_xor_sync(0xffffffffu, m[hh], off));
    }

    // ---- pass 2: sum of exp ----
    float ssum[HEADS];
#pragma unroll
    for (int hh = 0; hh < HEADS; hh++) ssum[hh] = 0.f;
    for (int i = start + lane; i < end; i += 32) {
        const int s = g_csr[i];
#pragma unroll
        for (int hh = 0; hh < HEADS; hh++) {
            float e = as[s * HEADS + hh] + adv[hh];
            e = (e >= 0.f) ? e : NEG_SLOPE * e;
            ssum[hh] += __expf(e - m[hh]);
        }
    }
#pragma unroll
    for (int hh = 0; hh < HEADS; hh++) {
#pragma unroll
        for (int off = 16; off > 0; off >>= 1)
            ssum[hh] += __shfl_xor_sync(0xffffffffu, ssum[hh], off);
    }
    float inv[HEADS];
#pragma unroll
    for (int hh = 0; hh < HEADS; hh++) inv[hh] = 1.0f / ssum[hh];

    // ---- pass 3: chunked weighted gather-accumulate ----
    const int head = (lane * RP) >> 6;   // which head my RP-channel chunk lives in
    float acc[RP];
#pragma unroll
    for (int r = 0; r < RP; r++) acc[r] = 0.f;

    for (int base = start; base < end; base += 32) {
        const int cnt = min(32, end - base);
        const int i = base + lane;
        if (lane < cnt) {
            const int s = g_csr[i];
            s_src[wslot][lane] = s;
#pragma unroll
            for (int hh = 0; hh < HEADS; hh++) {
                float e = as[s * HEADS + hh] + adv[hh];
                e = (e >= 0.f) ? e : NEG_SLOPE * e;
                s_w[wslot][lane][hh] = __expf(e - m[hh]) * inv[hh];
            }
        }
        __syncwarp();

#pragma unroll 2
        for (int j = 0; j < cnt; j++) {
            const int s   = s_src[wslot][j];
            const float w = s_w[wslot][j][head];
            const float* rowp = h + (size_t)s * D + lane * RP;
            if constexpr (RP == 8) {
                const float4 v0 = *reinterpret_cast<const float4*>(rowp);
                const float4 v1 = *reinterpret_cast<const float4*>(rowp + 4);
                acc[0] += w * v0.x; acc[1] += w * v0.y;
                acc[2] += w * v0.z; acc[3] += w * v0.w;
                acc[4] += w * v1.x; acc[5] += w * v1.y;
                acc[6] += w * v1.z; acc[7] += w * v1.w;
            } else {
                const float2 v0 = *reinterpret_cast<const float2*>(rowp);
                acc[0] += w * v0.x; acc[1] += w * v0.y;
            }
        }
        __syncwarp();
    }

    // ---- epilogue: + bias (, relu), store ----
    float* op = out + (size_t)warp * D + lane * RP;
#pragma unroll
    for (int r = 0; r < RP; r++) {
        float v = acc[r] + bias[lane * RP + r];
        if (L1) v = fmaxf(v, 0.f);
        acc[r] = v;
    }
    if constexpr (RP == 8) {
        *reinterpret_cast<float4*>(op)     = make_float4(acc[0], acc[1], acc[2], acc[3]);
        *reinterpret_cast<float4*>(op + 4) = make_float4(acc[4], acc[5], acc[6], acc[7]);
    } else {
        *reinterpret_cast<float2*>(op) = make_float2(acc[0], acc[1]);
    }
}

// ---------------------------------------------------------------------------
// Launch — kernel launches ONLY (graph-capturable)
// ---------------------------------------------------------------------------
extern "C" void kernel_launch(void* const* d_in, const int* in_sizes, int n_in,
                              void* d_out, int out_size)
{
    const float* x      = (const float*)d_in[0];
    const int*   ei     = (const int*)d_in[1];   // int32! (JAX x64 disabled)
    const float* W1     = (const float*)d_in[2];
    const float* a_src1 = (const float*)d_in[3];
    const float* a_dst1 = (const float*)d_in[4];
    const float* b1     = (const float*)d_in[5];
    const float* W2     = (const float*)d_in[6];
    const float* a_src2 = (const float*)d_in[7];
    const float* a_dst2 = (const float*)d_in[8];
    const float* b2     = (const float*)d_in[9];
    float*       out    = (float*)d_out;

    const int n = in_sizes[0] / IND;      // 50000
    const int E = in_sizes[1] / 2;        // 800000
    const int tot = E + n;

    const int nb256 = (n + 255) / 256;
    const int eb256 = (tot + 255) / 256;

    // ---- CSR build (shared by both layers) ----
    zero_deg_kernel<<<nb256, 256>>>(n);
    hist_kernel<<<eb256, 256>>>(ei, E, n);
    scan_kernel<<<1, 1024>>>(n);
    scatter_kernel<<<eb256, 256>>>(ei, E, n);

    // ---- layer 1 ----
    {
        dim3 grid(D1 / BN, (n + BM - 1) / BM);
        sgemm_kernel<1><<<grid, 256>>>(x, W1, n, D1, IND);
    }
    alpha1_kernel<<<nb256, 256>>>(a_src1, a_dst1, n);
    {
        const int grid = (n + AGG_WARPS - 1) / AGG_WARPS;
        agg_kernel<NHEADS, 8, true><<<grid, AGG_WARPS * 32>>>(b1, nullptr, n);
    }

    // ---- layer 2 ----
    {
        dim3 grid(D2 / BN, (n + BM - 1) / BM);
        sgemm_kernel<2><<<grid, 256>>>(nullptr, W2, n, D2, D1);
    }
    alpha2_kernel<<<nb256, 256>>>(a_src2, a_dst2, n);
    {
        const int grid = (n + AGG_WARPS - 1) / AGG_WARPS;
        agg_kernel<1, 2, false><<<grid, AGG_WARPS * 32>>>(b2, out, n);
    }
}

// round 6
// speedup vs baseline: 1.0263x; 1.0263x over previous
#include <cuda_runtime.h>
#include <cstdint>
#include <cmath>

// Problem constants (match reference_code)
#define NN     50000
#define EE     800000
#define ETOT   (NN + EE)
#define IND    256
#define HIDD   64
#define NHEADS 4
#define D1     256    // heads*hid layer 1 output width
#define D2     64     // layer 2 output width
#define NEG_SLOPE 0.2f

// ---------------------------------------------------------------------------
// Scratch (no allocations allowed -> __device__ globals)
// ---------------------------------------------------------------------------
__device__ __align__(16) float g_h1[(size_t)NN * D1];   // x @ W1
__device__ __align__(16) float g_hr[(size_t)NN * D1];   // relu(agg1 + b1)
__device__ __align__(16) float g_h2[(size_t)NN * D2];   // hr @ W2
__device__ __align__(16) float g_as1[NN * NHEADS];
__device__ __align__(16) float g_ad1[NN * NHEADS];
__device__ __align__(16) float g_as2[NN];
__device__ __align__(16) float g_ad2[NN];
__device__ int   g_deg[NN];
__device__ int   g_row[NN + 1];
__device__ int   g_cur[NN];
__device__ int   g_csr[ETOT];             // src node per (dst-sorted) edge

// ---------------------------------------------------------------------------
// High-throughput SGEMM: C[M,N] = A[M,K] @ B[K,N], K=256 both layers.
// LAYER=1: 128x128 tile, 8x8/thread.  LAYER=2: 128x64 tile, 8x4/thread.
// 256 threads, BK=16, double-buffered smem.
// ---------------------------------------------------------------------------
#define GBK 16

template <int LAYER>
__global__ void __launch_bounds__(256)
gemm_kernel(const float* __restrict__ Aext,
            const float* __restrict__ B, int M)
{
    constexpr int K   = (LAYER == 1) ? IND : D1;   // 256
    constexpr int N   = (LAYER == 1) ? D1  : D2;   // 256 / 64
    constexpr int BNc = (LAYER == 1) ? 128 : 64;
    constexpr int NC  = BNc / 64;                  // col chunks (2 / 1)
    constexpr int NT  = K / GBK;                   // 16 k-tiles
    constexpr int BSLOTS = GBK * (BNc / 4);        // float4 slots in B tile

    const float* __restrict__ A = (LAYER == 1) ? Aext : g_hr;
    float* __restrict__ C       = (LAYER == 1) ? g_h1 : g_h2;

    __shared__ __align__(16) float As[2][GBK][128];
    __shared__ __align__(16) float Bs[2][GBK][BNc];

    const int tid  = threadIdx.x;
    const int brow = blockIdx.y * 128;
    const int bcol = blockIdx.x * BNc;

    const int tx4 = (tid % 16) * 4;
    const int ty4 = (tid / 16) * 4;

    // A loader: 128x16 tile = 512 float4 slots, 2 per thread
    const int a_s0_row = tid >> 2;            // slot tid
    const int a_s0_c4  = (tid & 3) * 4;
    const int a_s1_row = (tid + 256) >> 2;    // slot tid+256
    const int a_s1_c4  = a_s0_c4;
    // B loader: GBK x BNc tile = BSLOTS float4 slots (512 or 256)
    const int b_s0_row = tid / (BNc / 4);
    const int b_s0_c4  = (tid % (BNc / 4)) * 4;
    const int b_s1_row = (tid + 256) / (BNc / 4);
    const int b_s1_c4  = b_s0_c4;

    float4 a_r0, a_r1, b_r0, b_r1;

    auto load_regs = [&](int k0) {
        const int gr0 = brow + a_s0_row;
        const int gr1 = brow + a_s1_row;
        a_r0 = (gr0 < M) ? *reinterpret_cast<const float4*>(A + (size_t)gr0 * K + k0 + a_s0_c4)
                         : make_float4(0.f, 0.f, 0.f, 0.f);
        a_r1 = (gr1 < M) ? *reinterpret_cast<const float4*>(A + (size_t)gr1 * K + k0 + a_s1_c4)
                         : make_float4(0.f, 0.f, 0.f, 0.f);
        b_r0 = *reinterpret_cast<const float4*>(B + (size_t)(k0 + b_s0_row) * N + bcol + b_s0_c4);
        if (BSLOTS > 256)
            b_r1 = *reinterpret_cast<const float4*>(B + (size_t)(k0 + b_s1_row) * N + bcol + b_s1_c4);
    };
    auto store_smem = [&](int buf) {
        As[buf][a_s0_c4 + 0][a_s0_row] = a_r0.x;
        As[buf][a_s0_c4 + 1][a_s0_row] = a_r0.y;
        As[buf][a_s0_c4 + 2][a_s0_row] = a_r0.z;
        As[buf][a_s0_c4 + 3][a_s0_row] = a_r0.w;
        As[buf][a_s1_c4 + 0][a_s1_row] = a_r1.x;
        As[buf][a_s1_c4 + 1][a_s1_row] = a_r1.y;
        As[buf][a_s1_c4 + 2][a_s1_row] = a_r1.z;
        As[buf][a_s1_c4 + 3][a_s1_row] = a_r1.w;
        *reinterpret_cast<float4*>(&Bs[buf][b_s0_row][b_s0_c4]) = b_r0;
        if (BSLOTS > 256)
            *reinterpret_cast<float4*>(&Bs[buf][b_s1_row][b_s1_c4]) = b_r1;
    };

    float acc[8][NC * 4];
#pragma unroll
    for (int i = 0; i < 8; i++)
#pragma unroll
        for (int j = 0; j < NC * 4; j++) acc[i][j] = 0.f;

    load_regs(0);
    store_smem(0);
    __syncthreads();

    for (int kt = 0; kt < NT; kt++) {
        const int cur = kt & 1;
        if (kt + 1 < NT) load_regs((kt + 1) * GBK);

#pragma unroll
        for (int k = 0; k < GBK; k++) {
            const float4 a0 = *reinterpret_cast<const float4*>(&As[cur][k][ty4]);
            const float4 a1 = *reinterpret_cast<const float4*>(&As[cur][k][ty4 + 64]);
            const float4 b0 = *reinterpret_cast<const float4*>(&Bs[cur][k][tx4]);
            float4 b1;
            if (NC == 2) b1 = *reinterpret_cast<const float4*>(&Bs[cur][k][tx4 + 64]);

            const float av[8] = {a0.x, a0.y, a0.z, a0.w, a1.x, a1.y, a1.z, a1.w};
            float bv[NC * 4];
            bv[0] = b0.x; bv[1] = b0.y; bv[2] = b0.z; bv[3] = b0.w;
            if (NC == 2) { bv[4] = b1.x; bv[5] = b1.y; bv[6] = b1.z; bv[7] = b1.w; }
#pragma unroll
            for (int i = 0; i < 8; i++)
#pragma unroll
                for (int j = 0; j < NC * 4; j++)
                    acc[i][j] += av[i] * bv[j];
        }

        if (kt + 1 < NT) {
            store_smem(cur ^ 1);
            __syncthreads();
        }
    }

    // Store C
#pragma unroll
    for (int ic = 0; ic < 2; ic++) {
#pragma unroll
        for (int i = 0; i < 4; i++) {
            const int gr = brow + ty4 + ic * 64 + i;
            if (gr < M) {
                float* cp = C + (size_t)gr * N + bcol;
                *reinterpret_cast<float4*>(cp + tx4) =
                    make_float4(acc[ic * 4 + i][0], acc[ic * 4 + i][1],
                                acc[ic * 4 + i][2], acc[ic * 4 + i][3]);
                if (NC == 2)
                    *reinterpret_cast<float4*>(cp + tx4 + 64) =
                        make_float4(acc[ic * 4 + i][4], acc[ic * 4 + i][5],
                                    acc[ic * 4 + i][6], acc[ic * 4 + i][7]);
            }
        }
    }
}

// ---------------------------------------------------------------------------
// Attention logit dot products
// ---------------------------------------------------------------------------
__global__ void alpha1_kernel(const float* __restrict__ a_src,
                              const float* __restrict__ a_dst, int n)
{
    const int i = blockIdx.x * blockDim.x + threadIdx.x;
    if (i >= n) return;
    const float4* row = reinterpret_cast<const float4*>(g_h1 + (size_t)i * D1);
    const float4* asv = reinterpret_cast<const float4*>(a_src);
    const float4* adv = reinterpret_cast<const float4*>(a_dst);
    float s[NHEADS] = {0.f, 0.f, 0.f, 0.f};
    float d[NHEADS] = {0.f, 0.f, 0.f, 0.f};
#pragma unroll
    for (int q = 0; q < D1 / 4; q++) {
        const float4 v = row[q];
        const float4 a = asv[q];
        const float4 b = adv[q];
        const int h = q >> 4;   // q*4/64
        s[h] += v.x * a.x + v.y * a.y + v.z * a.z + v.w * a.w;
        d[h] += v.x * b.x + v.y * b.y + v.z * b.z + v.w * b.w;
    }
#pragma unroll
    for (int h = 0; h < NHEADS; h++) {
        g_as1[i * NHEADS + h] = s[h];
        g_ad1[i * NHEADS + h] = d[h];
    }
}

__global__ void alpha2_kernel(const float* __restrict__ a_src,
                              const float* __restrict__ a_dst, int n)
{
    const int i = blockIdx.x * blockDim.x + threadIdx.x;
    if (i >= n) return;
    const float4* row = reinterpret_cast<const float4*>(g_h2 + (size_t)i * D2);
    const float4* asv = reinterpret_cast<const float4*>(a_src);
    const float4* adv = reinterpret_cast<const float4*>(a_dst);
    float s = 0.f, d = 0.f;
#pragma unroll
    for (int q = 0; q < D2 / 4; q++) {
        const float4 v = row[q];
        const float4 a = asv[q];
        const float4 b = adv[q];
        s += v.x * a.x + v.y * a.y + v.z * a.z + v.w * a.w;
        d += v.x * b.x + v.y * b.y + v.z * b.z + v.w * b.w;
    }
    g_as2[i] = s;
    g_ad2[i] = d;
}

// ---------------------------------------------------------------------------
// CSR build: histogram -> exclusive scan -> scatter  (edge_index is INT32)
// ---------------------------------------------------------------------------
__global__ void zero_deg_kernel(int n)
{
    const int i = blockIdx.x * blockDim.x + threadIdx.x;
    if (i < n) g_deg[i] = 0;
}

__global__ void hist_kernel(const int* __restrict__ ei, int E, int n)
{
    const int i = blockIdx.x * blockDim.x + threadIdx.x;
    const int tot = E + n;
    if (i >= tot) return;
    const int d = (i < E) ? ei[E + i] : (i - E);
    if ((unsigned)d < (unsigned)n)
        atomicAdd(&g_deg[d], 1);
}

__global__ void scan_kernel(int n)
{
    __shared__ int smem[1024];
    __shared__ int carry;
    const int tid = threadIdx.x;
    if (tid == 0) carry = 0;
    __syncthreads();
    for (int base = 0; base < n; base += 1024) {
        const int i = base + tid;
        const int v = (i < n) ? g_deg[i] : 0;
        int x = v;
#pragma unroll
        for (int off = 1; off < 1024; off <<= 1) {
            smem[tid] = x;
            __syncthreads();
            if (tid >= off) x += smem[tid - off];
            __syncthreads();
        }
        const int excl = x - v + carry;
        if (i < n) {
            g_row[i] = excl;
            g_cur[i] = excl;
        }
        __syncthreads();
        if (tid == 1023) carry += x;   // x of last thread = chunk total
        __syncthreads();
    }
    if (tid == 0) g_row[n] = carry;
}

__global__ void scatter_kernel(const int* __restrict__ ei, int E, int n)
{
    const int i = blockIdx.x * blockDim.x + threadIdx.x;
    const int tot = E + n;
    if (i >= tot) return;
    int s, d;
    if (i < E) {
        s = ei[i];
        d = ei[E + i];
    } else {
        s = d = i - E;
    }
    if ((unsigned)d < (unsigned)n && (unsigned)s < (unsigned)n) {
        const int pos = atomicAdd(&g_cur[d], 1);
        if ((unsigned)pos < (unsigned)ETOT)
            g_csr[pos] = s;
    }
}

// ---------------------------------------------------------------------------
// GAT aggregation, warp-per-destination (3-pass softmax, chunked gather).
// ---------------------------------------------------------------------------
#define AGG_WARPS 8

template <int HEADS, int RP, bool L1>
__global__ void __launch_bounds__(AGG_WARPS * 32)
agg_kernel(const float* __restrict__ bias,
           float* __restrict__ out_ext, int n)
{
    constexpr int D = RP * 32;
    const float* __restrict__ h  = L1 ? g_h1  : g_h2;
    const float* __restrict__ as = L1 ? g_as1 : g_as2;
    const float* __restrict__ ad = L1 ? g_ad1 : g_ad2;
    float* __restrict__ out      = L1 ? g_hr  : out_ext;

    __shared__ int   s_src[AGG_WARPS][32];
    __shared__ float s_w[AGG_WARPS][32][HEADS];

    const int warp  = (blockIdx.x * blockDim.x + threadIdx.x) >> 5;
    const int wslot = threadIdx.x >> 5;
    const int lane  = threadIdx.x & 31;
    if (warp >= n) return;

    const int start = g_row[warp];
    const int end   = g_row[warp + 1];

    float adv[HEADS];
#pragma unroll
    for (int hh = 0; hh < HEADS; hh++) adv[hh] = ad[warp * HEADS + hh];

    // ---- pass 1: max ----
    float m[HEADS];
#pragma unroll
    for (int hh = 0; hh < HEADS; hh++) m[hh] = -1e30f;
    for (int i = start + lane; i < end; i += 32) {
        const int s = g_csr[i];
#pragma unroll
        for (int hh = 0; hh < HEADS; hh++) {
            float e = as[s * HEADS + hh] + adv[hh];
            e = (e >= 0.f) ? e : NEG_SLOPE * e;
            m[hh] = fmaxf(m[hh], e);
        }
    }
#pragma unroll
    for (int hh = 0; hh < HEADS; hh++) {
#pragma unroll
        for (int off = 16; off > 0; off >>= 1)
            m[hh] = fmaxf(m[hh], __shfl_xor_sync(0xffffffffu, m[hh], off));
    }

    // ---- pass 2: sum of exp ----
    float ssum[HEADS];
#pragma unroll
    for (int hh = 0; hh < HEADS; hh++) ssum[hh] = 0.f;
    for (int i = start + lane; i < end; i += 32) {
        const int s = g_csr[i];
#pragma unroll
        for (int hh = 0; hh < HEADS; hh++) {
            float e = as[s * HEADS + hh] + adv[hh];
            e = (e >= 0.f) ? e : NEG_SLOPE * e;
            ssum[hh] += __expf(e - m[hh]);
        }
    }
#pragma unroll
    for (int hh = 0; hh < HEADS; hh++) {
#pragma unroll
        for (int off = 16; off > 0; off >>= 1)
            ssum[hh] += __shfl_xor_sync(0xffffffffu, ssum[hh], off);
    }
    float inv[HEADS];
#pragma unroll
    for (int hh = 0; hh < HEADS; hh++) inv[hh] = 1.0f / ssum[hh];

    // ---- pass 3: chunked weighted gather-accumulate ----
    const int head = (lane * RP) >> 6;   // which head my RP-channel chunk lives in
    float acc[RP];
#pragma unroll
    for (int r = 0; r < RP; r++) acc[r] = 0.f;

    for (int base = start; base < end; base += 32) {
        const int cnt = min(32, end - base);
        const int i = base + lane;
        if (lane < cnt) {
            const int s = g_csr[i];
            s_src[wslot][lane] = s;
#pragma unroll
            for (int hh = 0; hh < HEADS; hh++) {
                float e = as[s * HEADS + hh] + adv[hh];
                e = (e >= 0.f) ? e : NEG_SLOPE * e;
                s_w[wslot][lane][hh] = __expf(e - m[hh]) * inv[hh];
            }
        }
        __syncwarp();

#pragma unroll 2
        for (int j = 0; j < cnt; j++) {
            const int s   = s_src[wslot][j];
            const float w = s_w[wslot][j][head];
            const float* rowp = h + (size_t)s * D + lane * RP;
            if constexpr (RP == 8) {
                const float4 v0 = *reinterpret_cast<const float4*>(rowp);
                const float4 v1 = *reinterpret_cast<const float4*>(rowp + 4);
                acc[0] += w * v0.x; acc[1] += w * v0.y;
                acc[2] += w * v0.z; acc[3] += w * v0.w;
                acc[4] += w * v1.x; acc[5] += w * v1.y;
                acc[6] += w * v1.z; acc[7] += w * v1.w;
            } else {
                const float2 v0 = *reinterpret_cast<const float2*>(rowp);
                acc[0] += w * v0.x; acc[1] += w * v0.y;
            }
        }
        __syncwarp();
    }

    // ---- epilogue: + bias (, relu), store ----
    float* op = out + (size_t)warp * D + lane * RP;
#pragma unroll
    for (int r = 0; r < RP; r++) {
        float v = acc[r] + bias[lane * RP + r];
        if (L1) v = fmaxf(v, 0.f);
        acc[r] = v;
    }
    if constexpr (RP == 8) {
        *reinterpret_cast<float4*>(op)     = make_float4(acc[0], acc[1], acc[2], acc[3]);
        *reinterpret_cast<float4*>(op + 4) = make_float4(acc[4], acc[5], acc[6], acc[7]);
    } else {
        *reinterpret_cast<float2*>(op) = make_float2(acc[0], acc[1]);
    }
}

// ---------------------------------------------------------------------------
// Launch — kernel launches ONLY (graph-capturable)
// ---------------------------------------------------------------------------
extern "C" void kernel_launch(void* const* d_in, const int* in_sizes, int n_in,
                              void* d_out, int out_size)
{
    const float* x      = (const float*)d_in[0];
    const int*   ei     = (const int*)d_in[1];   // int32! (JAX x64 disabled)
    const float* W1     = (const float*)d_in[2];
    const float* a_src1 = (const float*)d_in[3];
    const float* a_dst1 = (const float*)d_in[4];
    const float* b1     = (const float*)d_in[5];
    const float* W2     = (const float*)d_in[6];
    const float* a_src2 = (const float*)d_in[7];
    const float* a_dst2 = (const float*)d_in[8];
    const float* b2     = (const float*)d_in[9];
    float*       out    = (float*)d_out;

    const int n = in_sizes[0] / IND;      // 50000
    const int E = in_sizes[1] / 2;        // 800000
    const int tot = E + n;

    const int nb256 = (n + 255) / 256;
    const int eb256 = (tot + 255) / 256;

    // ---- CSR build (shared by both layers) ----
    zero_deg_kernel<<<nb256, 256>>>(n);
    hist_kernel<<<eb256, 256>>>(ei, E, n);
    scan_kernel<<<1, 1024>>>(n);
    scatter_kernel<<<eb256, 256>>>(ei, E, n);

    // ---- layer 1 ----
    {
        dim3 grid(D1 / 128, (n + 127) / 128);
        gemm_kernel<1><<<grid, 256>>>(x, W1, n);
    }
    alpha1_kernel<<<nb256, 256>>>(a_src1, a_dst1, n);
    {
        const int grid = (n + AGG_WARPS - 1) / AGG_WARPS;
        agg_kernel<NHEADS, 8, true><<<grid, AGG_WARPS * 32>>>(b1, nullptr, n);
    }

    // ---- layer 2 ----
    {
        dim3 grid(D2 / 64, (n + 127) / 128);
        gemm_kernel<2><<<grid, 256>>>(nullptr, W2, n);
    }
    alpha2_kernel<<<nb256, 256>>>(a_src2, a_dst2, n);
    {
        const int grid = (n + AGG_WARPS - 1) / AGG_WARPS;
        agg_kernel<1, 2, false><<<grid, AGG_WARPS * 32>>>(b2, out, n);
    }
}

// round 8
// speedup vs baseline: 1.6143x; 1.5729x over previous
#include <cuda_runtime.h>
#include <cuda_bf16.h>
#include <cstdint>
#include <cmath>

// Problem constants (match reference_code)
#define NN     50000
#define EE     800000
#define ETOT   (NN + EE)
#define IND    256
#define HIDD   64
#define NHEADS 4
#define D1     256    // heads*hid layer 1 output width
#define D2     64     // layer 2 output width
#define NEG_SLOPE 0.2f

// ---------------------------------------------------------------------------
// Scratch (__device__ globals; no runtime API in kernel_launch)
// ---------------------------------------------------------------------------
__device__ __align__(16) float g_h1[(size_t)NN * D1];   // x @ W1 (fp32)
__device__ __align__(16) float g_h2[(size_t)NN * D2];   // hr @ W2 (fp32)
__device__ __align__(16) __nv_bfloat16 g_xh[(size_t)NN * IND];
__device__ __align__(16) __nv_bfloat16 g_xl[(size_t)NN * IND];
__device__ __align__(16) __nv_bfloat16 g_w1h[IND * D1];
__device__ __align__(16) __nv_bfloat16 g_w1l[IND * D1];
__device__ __align__(16) __nv_bfloat16 g_w2h[D1 * D2];
__device__ __align__(16) __nv_bfloat16 g_w2l[D1 * D2];
__device__ __align__(16) __nv_bfloat16 g_hrh[(size_t)NN * D1];  // relu(agg1+b1) hi
__device__ __align__(16) __nv_bfloat16 g_hrl[(size_t)NN * D1];  // lo
__device__ __align__(16) float g_as1[NN * NHEADS];
__device__ __align__(16) float g_ad1[NN * NHEADS];
__device__ __align__(16) float g_as2[NN];
__device__ __align__(16) float g_ad2[NN];
__device__ int   g_deg[NN];
__device__ int   g_row[NN + 1];
__device__ int   g_cur[NN];
__device__ int   g_csr[ETOT];
__device__ int   g_bsum[64];
__device__ int   g_boff[64];

// ---------------------------------------------------------------------------
// PTX helpers: ldmatrix + bf16 mma
// ---------------------------------------------------------------------------
__device__ __forceinline__ uint32_t sptr(const void* p) {
    return (uint32_t)__cvta_generic_to_shared(p);
}
__device__ __forceinline__ void ldsm4(uint32_t* r, uint32_t a) {
    asm volatile("ldmatrix.sync.aligned.m8n8.x4.shared.b16 {%0,%1,%2,%3}, [%4];"
                 : "=r"(r[0]), "=r"(r[1]), "=r"(r[2]), "=r"(r[3]) : "r"(a));
}
__device__ __forceinline__ void ldsm4t(uint32_t* r, uint32_t a) {
    asm volatile("ldmatrix.sync.aligned.m8n8.x4.trans.shared.b16 {%0,%1,%2,%3}, [%4];"
                 : "=r"(r[0]), "=r"(r[1]), "=r"(r[2]), "=r"(r[3]) : "r"(a));
}
__device__ __forceinline__ void mma16816(float* c, const uint32_t* a, const uint32_t* b) {
    asm volatile(
        "mma.sync.aligned.m16n8k16.row.col.f32.bf16.bf16.f32 "
        "{%0,%1,%2,%3},{%4,%5,%6,%7},{%8,%9},{%0,%1,%2,%3};"
        : "+f"(c[0]), "+f"(c[1]), "+f"(c[2]), "+f"(c[3])
        : "r"(a[0]), "r"(a[1]), "r"(a[2]), "r"(a[3]), "r"(b[0]), "r"(b[1]));
}

// ---------------------------------------------------------------------------
// fp32 -> bf16 hi/lo split.  which: 0=x, 1=W1, 2=W2
// ---------------------------------------------------------------------------
__global__ void split_kernel(const float* __restrict__ src, int which, int n4)
{
    __nv_bfloat16* hi;
    __nv_bfloat16* lo;
    if (which == 0)      { hi = g_xh;  lo = g_xl;  }
    else if (which == 1) { hi = g_w1h; lo = g_w1l; }
    else                 { hi = g_w2h; lo = g_w2l; }

    const int i = blockIdx.x * blockDim.x + threadIdx.x;
    if (i >= n4) return;
    const float4 v = reinterpret_cast<const float4*>(src)[i];
    float vv[4] = {v.x, v.y, v.z, v.w};
    __nv_bfloat16 h[4], l[4];
#pragma unroll
    for (int q = 0; q < 4; q++) {
        h[q] = __float2bfloat16(vv[q]);
        l[q] = __float2bfloat16(vv[q] - __bfloat162float(h[q]));
    }
    reinterpret_cast<__nv_bfloat162*>(hi)[2 * i + 0] = __nv_bfloat162{h[0], h[1]};
    reinterpret_cast<__nv_bfloat162*>(hi)[2 * i + 1] = __nv_bfloat162{h[2], h[3]};
    reinterpret_cast<__nv_bfloat162*>(lo)[2 * i + 0] = __nv_bfloat162{l[0], l[1]};
    reinterpret_cast<__nv_bfloat162*>(lo)[2 * i + 1] = __nv_bfloat162{l[2], l[3]};
}

// ---------------------------------------------------------------------------
// Tensor-core GEMM, bf16 x 3-term split, fp32 accum.
// C[M,N] = (Ah+Al) @ (Bh+Bl)  ~= AhBh + AhBl + AlBh
// LAYER=1: A=g_xh/xl [M,256], B=g_w1h/l [256,256], C=g_h1, BN=128
// LAYER=2: A=g_hrh/l [M,256], B=g_w2h/l [256,64],  C=g_h2, BN=64
// Block 128xBN, 8 warps (4 m x 2 n), warp tile 32 x BN/2, BK=32.
// ---------------------------------------------------------------------------
template <int LAYER>
__global__ void __launch_bounds__(256)
mma_gemm_kernel(int M)
{
    constexpr int K  = 256;
    constexpr int N  = (LAYER == 1) ? D1 : D2;
    constexpr int BN = (LAYER == 1) ? 128 : 64;
    constexpr int BM = 128;
    constexpr int BK = 32;
    constexpr int KP = BK + 8;       // padded A row (bf16)
    constexpr int NP = BN + 8;       // padded B row (bf16)
    constexpr int NT = BN / 16;      // n8 frags per warp (8 / 4)
    constexpr int NBL = (BK * BN / 8) / 256;   // B uint4 slots per thread (2 / 1)

    const __nv_bfloat16* __restrict__ Ah = (LAYER == 1) ? g_xh  : g_hrh;
    const __nv_bfloat16* __restrict__ Al = (LAYER == 1) ? g_xl  : g_hrl;
    const __nv_bfloat16* __restrict__ Bh = (LAYER == 1) ? g_w1h : g_w2h;
    const __nv_bfloat16* __restrict__ Bl = (LAYER == 1) ? g_w1l : g_w2l;
    float* __restrict__ C                = (LAYER == 1) ? g_h1  : g_h2;

    __shared__ __align__(16) __nv_bfloat16 sAh[BM][KP], sAl[BM][KP];
    __shared__ __align__(16) __nv_bfloat16 sBh[BK][NP], sBl[BK][NP];

    const int tid  = threadIdx.x;
    const int lane = tid & 31;
    const int wid  = tid >> 5;
    const int wm   = (wid & 3) * 32;
    const int wn   = (wid >> 2) * (BN / 2);
    const int brow = blockIdx.y * BM;
    const int bcol = blockIdx.x * BN;

    // A loader: 512 uint4 slots (128 rows x 4), 2 per thread
    const int ar0 = tid >> 2, ar1 = (tid + 256) >> 2;
    const int ak  = (tid & 3) * 8;

    uint4 ua_h[2], ua_l[2], ub_h[NBL], ub_l[NBL];

    auto gload = [&](int k0) {
        const int rows[2] = {ar0, ar1};
#pragma unroll
        for (int s = 0; s < 2; s++) {
            const int gr = brow + rows[s];
            if (gr < M) {
                const size_t off = (size_t)gr * K + k0 + ak;
                ua_h[s] = *reinterpret_cast<const uint4*>(Ah + off);
                ua_l[s] = *reinterpret_cast<const uint4*>(Al + off);
            } else {
                ua_h[s] = make_uint4(0, 0, 0, 0);
                ua_l[s] = make_uint4(0, 0, 0, 0);
            }
        }
#pragma unroll
        for (int s = 0; s < NBL; s++) {
            const int slot = tid + s * 256;
            const int kr = slot / (BN / 8);
            const int nc = (slot % (BN / 8)) * 8;
            const size_t off = (size_t)(k0 + kr) * N + bcol + nc;
            ub_h[s] = *reinterpret_cast<const uint4*>(Bh + off);
            ub_l[s] = *reinterpret_cast<const uint4*>(Bl + off);
        }
    };
    auto sstore = [&]() {
        const int rows[2] = {ar0, ar1};
#pragma unroll
        for (int s = 0; s < 2; s++) {
            *reinterpret_cast<uint4*>(&sAh[rows[s]][ak]) = ua_h[s];
            *reinterpret_cast<uint4*>(&sAl[rows[s]][ak]) = ua_l[s];
        }
#pragma unroll
        for (int s = 0; s < NBL; s++) {
            const int slot = tid + s * 256;
            const int kr = slot / (BN / 8);
            const int nc = (slot % (BN / 8)) * 8;
            *reinterpret_cast<uint4*>(&sBh[kr][nc]) = ub_h[s];
            *reinterpret_cast<uint4*>(&sBl[kr][nc]) = ub_l[s];
        }
    };

    float c[2][NT][4];
#pragma unroll
    for (int i = 0; i < 2; i++)
#pragma unroll
        for (int j = 0; j < NT; j++)
#pragma unroll
            for (int q = 0; q < 4; q++) c[i][j][q] = 0.f;

    gload(0);
    sstore();
    __syncthreads();

    constexpr int NKT = K / BK;   // 8
    for (int kt = 0; kt < NKT; kt++) {
        if (kt + 1 < NKT) gload((kt + 1) * BK);

#pragma unroll
        for (int ks = 0; ks < 2; ks++) {
            const int k16 = ks * 16;
            uint32_t fa_h[2][4], fa_l[2][4];
#pragma unroll
            for (int i = 0; i < 2; i++) {
                const int row = wm + i * 16 + (lane & 15);
                const int col = k16 + 8 * (lane >> 4);
                ldsm4(fa_h[i], sptr(&sAh[row][col]));
                ldsm4(fa_l[i], sptr(&sAl[row][col]));
            }
            uint32_t fb_h[NT][2], fb_l[NT][2];
#pragma unroll
            for (int j = 0; j < NT / 2; j++) {
                const int rr = k16 + (lane & 15);
                const int cc = wn + j * 16 + 8 * (lane >> 4);
                uint32_t t[4];
                ldsm4t(t, sptr(&sBh[rr][cc]));
                fb_h[2 * j][0] = t[0]; fb_h[2 * j][1] = t[1];
                fb_h[2 * j + 1][0] = t[2]; fb_h[2 * j + 1][1] = t[3];
                ldsm4t(t, sptr(&sBl[rr][cc]));
                fb_l[2 * j][0] = t[0]; fb_l[2 * j][1] = t[1];
                fb_l[2 * j + 1][0] = t[2]; fb_l[2 * j + 1][1] = t[3];
            }
#pragma unroll
            for (int i = 0; i < 2; i++)
#pragma unroll
                for (int j = 0; j < NT; j++) {
                    mma16816(c[i][j], fa_h[i], fb_h[j]);
                    mma16816(c[i][j], fa_h[i], fb_l[j]);
                    mma16816(c[i][j], fa_l[i], fb_h[j]);
                }
        }

        __syncthreads();
        if (kt + 1 < NKT) {
            sstore();
            __syncthreads();
        }
    }

    // Epilogue
#pragma unroll
    for (int i = 0; i < 2; i++) {
#pragma unroll
        for (int j = 0; j < NT; j++) {
            const int r   = brow + wm + i * 16 + (lane >> 2);
            const int col = bcol + wn + j * 8 + (lane & 3) * 2;
            if (r < M)
                *reinterpret_cast<float2*>(C + (size_t)r * N + col) =
                    make_float2(c[i][j][0], c[i][j][1]);
            if (r + 8 < M)
                *reinterpret_cast<float2*>(C + (size_t)(r + 8) * N + col) =
                    make_float2(c[i][j][2], c[i][j][3]);
        }
    }
}

// ---------------------------------------------------------------------------
// Attention logit dot products
// ---------------------------------------------------------------------------
__global__ void alpha1_kernel(const float* __restrict__ a_src,
                              const float* __restrict__ a_dst, int n)
{
    const int i = blockIdx.x * blockDim.x + threadIdx.x;
    if (i >= n) return;
    const float4* row = reinterpret_cast<const float4*>(g_h1 + (size_t)i * D1);
    const float4* asv = reinterpret_cast<const float4*>(a_src);
    const float4* adv = reinterpret_cast<const float4*>(a_dst);
    float s[NHEADS] = {0.f, 0.f, 0.f, 0.f};
    float d[NHEADS] = {0.f, 0.f, 0.f, 0.f};
#pragma unroll
    for (int q = 0; q < D1 / 4; q++) {
        const float4 v = row[q];
        const float4 a = asv[q];
        const float4 b = adv[q];
        const int h = q >> 4;
        s[h] += v.x * a.x + v.y * a.y + v.z * a.z + v.w * a.w;
        d[h] += v.x * b.x + v.y * b.y + v.z * b.z + v.w * b.w;
    }
#pragma unroll
    for (int h = 0; h < NHEADS; h++) {
        g_as1[i * NHEADS + h] = s[h];
        g_ad1[i * NHEADS + h] = d[h];
    }
}

__global__ void alpha2_kernel(const float* __restrict__ a_src,
                              const float* __restrict__ a_dst, int n)
{
    const int i = blockIdx.x * blockDim.x + threadIdx.x;
    if (i >= n) return;
    const float4* row = reinterpret_cast<const float4*>(g_h2 + (size_t)i * D2);
    const float4* asv = reinterpret_cast<const float4*>(a_src);
    const float4* adv = reinterpret_cast<const float4*>(a_dst);
    float s = 0.f, d = 0.f;
#pragma unroll
    for (int q = 0; q < D2 / 4; q++) {
        const float4 v = row[q];
        const float4 a = asv[q];
        const float4 b = adv[q];
        s += v.x * a.x + v.y * a.y + v.z * a.z + v.w * a.w;
        d += v.x * b.x + v.y * b.y + v.z * b.z + v.w * b.w;
    }
    g_as2[i] = s;
    g_ad2[i] = d;
}

// ---------------------------------------------------------------------------
// CSR build: histogram -> parallel 3-phase scan -> scatter (edge_index INT32)
// ---------------------------------------------------------------------------
__global__ void zero_deg_kernel(int n)
{
    const int i = blockIdx.x * blockDim.x + threadIdx.x;
    if (i < n) g_deg[i] = 0;
}

__global__ void hist_kernel(const int* __restrict__ ei, int E, int n)
{
    const int i = blockIdx.x * blockDim.x + threadIdx.x;
    const int tot = E + n;
    if (i >= tot) return;
    const int d = (i < E) ? ei[E + i] : (i - E);
    if ((unsigned)d < (unsigned)n)
        atomicAdd(&g_deg[d], 1);
}

__global__ void scan1_kernel(int n)
{
    __shared__ int smem[1024];
    const int tid = threadIdx.x;
    const int i = blockIdx.x * 1024 + tid;
    const int v = (i < n) ? g_deg[i] : 0;
    int x = v;
#pragma unroll
    for (int off = 1; off < 1024; off <<= 1) {
        smem[tid] = x;
        __syncthreads();
        if (tid >= off) x += smem[tid - off];
        __syncthreads();
    }
    if (i < n) g_row[i] = x - v;       // local exclusive
    if (tid == 1023) g_bsum[blockIdx.x] = x;
}

__global__ void scan2_kernel(int nb, int n)
{
    __shared__ int sm[64];
    const int tid = threadIdx.x;        // 64 threads
    const int v = (tid < nb) ? g_bsum[tid] : 0;
    int x = v;
#pragma unroll
    for (int off = 1; off < 64; off <<= 1) {
        sm[tid] = x;
        __syncthreads();
        if (tid >= off) x += sm[tid - off];
        __syncthreads();
    }
    if (tid < nb) g_boff[tid] = x - v;
    if (tid == 63) g_row[n] = x;        // grand total
}

__global__ void scan3_kernel(int n)
{
    const int i = blockIdx.x * blockDim.x + threadIdx.x;
    if (i >= n) return;
    const int v = g_row[i] + g_boff[i >> 10];
    g_row[i] = v;
    g_cur[i] = v;
}

__global__ void scatter_kernel(const int* __restrict__ ei, int E, int n)
{
    const int i = blockIdx.x * blockDim.x + threadIdx.x;
    const int tot = E + n;
    if (i >= tot) return;
    int s, d;
    if (i < E) {
        s = ei[i];
        d = ei[E + i];
    } else {
        s = d = i - E;
    }
    if ((unsigned)d < (unsigned)n && (unsigned)s < (unsigned)n) {
        const int pos = atomicAdd(&g_cur[d], 1);
        if ((unsigned)pos < (unsigned)ETOT)
            g_csr[pos] = s;
    }
}

// ---------------------------------------------------------------------------
// GAT aggregation, warp-per-destination (3-pass softmax, chunked gather).
// L1: gathers g_h1, outputs bf16 hi/lo split (g_hrh/g_hrl) after bias+relu.
// L2: gathers g_h2, outputs fp32 to d_out.
// ---------------------------------------------------------------------------
#define AGG_WARPS 8

template <int HEADS, int RP, bool L1>
__global__ void __launch_bounds__(AGG_WARPS * 32)
agg_kernel(const float* __restrict__ bias,
           float* __restrict__ out_ext, int n)
{
    constexpr int D = RP * 32;
    const float* __restrict__ h  = L1 ? g_h1  : g_h2;
    const float* __restrict__ as = L1 ? g_as1 : g_as2;
    const float* __restrict__ ad = L1 ? g_ad1 : g_ad2;

    __shared__ int   s_src[AGG_WARPS][32];
    __shared__ float s_w[AGG_WARPS][32][HEADS];

    const int warp  = (blockIdx.x * blockDim.x + threadIdx.x) >> 5;
    const int wslot = threadIdx.x >> 5;
    const int lane  = threadIdx.x & 31;
    if (warp >= n) return;

    const int start = g_row[warp];
    const int end   = g_row[warp + 1];

    float adv[HEADS];
#pragma unroll
    for (int hh = 0; hh < HEADS; hh++) adv[hh] = ad[warp * HEADS + hh];

    // ---- pass 1: max ----
    float m[HEADS];
#pragma unroll
    for (int hh = 0; hh < HEADS; hh++) m[hh] = -1e30f;
    for (int i = start + lane; i < end; i += 32) {
        const int s = g_csr[i];
#pragma unroll
        for (int hh = 0; hh < HEADS; hh++) {
            float e = as[s * HEADS + hh] + adv[hh];
            e = (e >= 0.f) ? e : NEG_SLOPE * e;
            m[hh] = fmaxf(m[hh], e);
        }
    }
#pragma unroll
    for (int hh = 0; hh < HEADS; hh++) {
#pragma unroll
        for (int off = 16; off > 0; off >>= 1)
            m[hh] = fmaxf(m[hh], __shfl_xor_sync(0xffffffffu, m[hh], off));
    }

    // ---- pass 2: sum of exp ----
    float ssum[HEADS];
#pragma unroll
    for (int hh = 0; hh < HEADS; hh++) ssum[hh] = 0.f;
    for (int i = start + lane; i < end; i += 32) {
        const int s = g_csr[i];
#pragma unroll
        for (int hh = 0; hh < HEADS; hh++) {
            float e = as[s * HEADS + hh] + adv[hh];
            e = (e >= 0.f) ? e : NEG_SLOPE * e;
            ssum[hh] += __expf(e - m[hh]);
        }
    }
#pragma unroll
    for (int hh = 0; hh < HEADS; hh++) {
#pragma unroll
        for (int off = 16; off > 0; off >>= 1)
            ssum[hh] += __shfl_xor_sync(0xffffffffu, ssum[hh], off);
    }
    float inv[HEADS];
#pragma unroll
    for (int hh = 0; hh < HEADS; hh++) inv[hh] = 1.0f / ssum[hh];

    // ---- pass 3: chunked weighted gather-accumulate ----
    const int head = (lane * RP) >> 6;
    float acc[RP];
#pragma unroll
    for (int r = 0; r < RP; r++) acc[r] = 0.f;

    for (int base = start; base < end; base += 32) {
        const int cnt = min(32, end - base);
        const int i = base + lane;
        if (lane < cnt) {
            const int s = g_csr[i];
            s_src[wslot][lane] = s;
#pragma unroll
            for (int hh = 0; hh < HEADS; hh++) {
                float e = as[s * HEADS + hh] + adv[hh];
                e = (e >= 0.f) ? e : NEG_SLOPE * e;
                s_w[wslot][lane][hh] = __expf(e - m[hh]) * inv[hh];
            }
        }
        __syncwarp();

#pragma unroll 2
        for (int j = 0; j < cnt; j++) {
            const int s   = s_src[wslot][j];
            const float w = s_w[wslot][j][head];
            const float* rowp = h + (size_t)s * D + lane * RP;
            if constexpr (RP == 8) {
                const float4 v0 = *reinterpret_cast<const float4*>(rowp);
                const float4 v1 = *reinterpret_cast<const float4*>(rowp + 4);
                acc[0] += w * v0.x; acc[1] += w * v0.y;
                acc[2] += w * v0.z; acc[3] += w * v0.w;
                acc[4] += w * v1.x; acc[5] += w * v1.y;
                acc[6] += w * v1.z; acc[7] += w * v1.w;
            } else {
                const float2 v0 = *reinterpret_cast<const float2*>(rowp);
                acc[0] += w * v0.x; acc[1] += w * v0.y;
            }
        }
        __syncwarp();
    }

    // ---- epilogue ----
#pragma unroll
    for (int r = 0; r < RP; r++) {
        float v = acc[r] + bias[lane * RP + r];
        if (L1) v = fmaxf(v, 0.f);
        acc[r] = v;
    }
    if constexpr (L1) {
        // bf16 hi/lo split for tensor-core GEMM2 consumption
        __nv_bfloat16 hb[RP], lb[RP];
#pragma unroll
        for (int r = 0; r < RP; r++) {
            hb[r] = __float2bfloat16(acc[r]);
            lb[r] = __float2bfloat16(acc[r] - __bfloat162float(hb[r]));
        }
        const size_t o = (size_t)warp * D + lane * RP;
        __nv_bfloat162* oh = reinterpret_cast<__nv_bfloat162*>(g_hrh + o);
        __nv_bfloat162* ol = reinterpret_cast<__nv_bfloat162*>(g_hrl + o);
#pragma unroll
        for (int r = 0; r < RP / 2; r++) {
            oh[r] = __nv_bfloat162{hb[2 * r], hb[2 * r + 1]};
            ol[r] = __nv_bfloat162{lb[2 * r], lb[2 * r + 1]};
        }
    } else {
        float* op = out_ext + (size_t)warp * D + lane * RP;
        *reinterpret_cast<float2*>(op) = make_float2(acc[0], acc[1]);
    }
}

// ---------------------------------------------------------------------------
// Launch — kernel launches ONLY (graph-capturable)
// ---------------------------------------------------------------------------
extern "C" void kernel_launch(void* const* d_in, const int* in_sizes, int n_in,
                              void* d_out, int out_size)
{
    const float* x      = (const float*)d_in[0];
    const int*   ei     = (const int*)d_in[1];   // int32 (JAX x64 disabled)
    const float* W1     = (const float*)d_in[2];
    const float* a_src1 = (const float*)d_in[3];
    const float* a_dst1 = (const float*)d_in[4];
    const float* b1     = (const float*)d_in[5];
    const float* W2     = (const float*)d_in[6];
    const float* a_src2 = (const float*)d_in[7];
    const float* a_dst2 = (const float*)d_in[8];
    const float* b2     = (const float*)d_in[9];
    float*       out    = (float*)d_out;

    const int n = in_sizes[0] / IND;      // 50000
    const int E = in_sizes[1] / 2;        // 800000
    const int tot = E + n;

    const int nb256 = (n + 255) / 256;
    const int eb256 = (tot + 255) / 256;
    const int nscan = (n + 1023) / 1024;

    // ---- bf16 splits ----
    {
        const int x4 = (n * IND) / 4;
        split_kernel<<<(x4 + 255) / 256, 256>>>(x, 0, x4);
        split_kernel<<<(IND * D1 / 4 + 255) / 256, 256>>>(W1, 1, IND * D1 / 4);
        split_kernel<<<(D1 * D2 / 4 + 255) / 256, 256>>>(W2, 2, D1 * D2 / 4);
    }

    // ---- CSR build ----
    zero_deg_kernel<<<nb256, 256>>>(n);
    hist_kernel<<<eb256, 256>>>(ei, E, n);
    scan1_kernel<<<nscan, 1024>>>(n);
    scan2_kernel<<<1, 64>>>(nscan, n);
    scan3_kernel<<<nb256, 256>>>(n);
    scatter_kernel<<<eb256, 256>>>(ei, E, n);

    // ---- layer 1 ----
    {
        dim3 grid(D1 / 128, (n + 127) / 128);
        mma_gemm_kernel<1><<<grid, 256>>>(n);
    }
    alpha1_kernel<<<nb256, 256>>>(a_src1, a_dst1, n);
    {
        const int grid = (n + AGG_WARPS - 1) / AGG_WARPS;
        agg_kernel<NHEADS, 8, true><<<grid, AGG_WARPS * 32>>>(b1, nullptr, n);
    }

    // ---- layer 2 ----
    {
        dim3 grid(D2 / 64, (n + 127) / 128);
        mma_gemm_kernel<2><<<grid, 256>>>(n);
    }
    alpha2_kernel<<<nb256, 256>>>(a_src2, a_dst2, n);
    {
        const int grid = (n + AGG_WARPS - 1) / AGG_WARPS;
        agg_kernel<1, 2, false><<<grid, AGG_WARPS * 32>>>(b2, out, n);
    }
}

// round 9
// speedup vs baseline: 1.8380x; 1.1386x over previous
#include <cuda_runtime.h>
#include <cuda_bf16.h>
#include <cstdint>
#include <cmath>

// Problem constants (match reference_code)
#define NN     50000
#define EE     800000
#define ETOT   (NN + EE)
#define IND    256
#define HIDD   64
#define NHEADS 4
#define D1     256
#define D2     64
#define NEG_SLOPE 0.2f

// ---------------------------------------------------------------------------
// Scratch
// ---------------------------------------------------------------------------
__device__ __align__(16) float g_h1[(size_t)NN * D1];
__device__ __align__(16) float g_h2[(size_t)NN * D2];
__device__ __align__(16) __nv_bfloat16 g_xh[(size_t)NN * IND];
__device__ __align__(16) __nv_bfloat16 g_xl[(size_t)NN * IND];
__device__ __align__(16) __nv_bfloat16 g_w1h[IND * D1];
__device__ __align__(16) __nv_bfloat16 g_w1l[IND * D1];
__device__ __align__(16) __nv_bfloat16 g_w2h[D1 * D2];
__device__ __align__(16) __nv_bfloat16 g_w2l[D1 * D2];
__device__ __align__(16) __nv_bfloat16 g_hrh[(size_t)NN * D1];
__device__ __align__(16) __nv_bfloat16 g_hrl[(size_t)NN * D1];
__device__ __align__(16) float g_as1[NN * NHEADS];
__device__ __align__(16) float g_ad1[NN * NHEADS];
__device__ __align__(16) float g_as2[NN];
__device__ __align__(16) float g_ad2[NN];
__device__ int   g_deg[NN];
__device__ int   g_row[NN + 1];
__device__ int   g_cur[NN];
__device__ int   g_csr[ETOT];
__device__ int   g_bsum[64];
__device__ int   g_boff[64];

// ---------------------------------------------------------------------------
// PTX helpers
// ---------------------------------------------------------------------------
__device__ __forceinline__ uint32_t sptr(const void* p) {
    return (uint32_t)__cvta_generic_to_shared(p);
}
__device__ __forceinline__ void ldsm4(uint32_t* r, uint32_t a) {
    asm volatile("ldmatrix.sync.aligned.m8n8.x4.shared.b16 {%0,%1,%2,%3}, [%4];"
                 : "=r"(r[0]), "=r"(r[1]), "=r"(r[2]), "=r"(r[3]) : "r"(a));
}
__device__ __forceinline__ void ldsm4t(uint32_t* r, uint32_t a) {
    asm volatile("ldmatrix.sync.aligned.m8n8.x4.trans.shared.b16 {%0,%1,%2,%3}, [%4];"
                 : "=r"(r[0]), "=r"(r[1]), "=r"(r[2]), "=r"(r[3]) : "r"(a));
}
__device__ __forceinline__ void mma16816(float* c, const uint32_t* a, const uint32_t* b) {
    asm volatile(
        "mma.sync.aligned.m16n8k16.row.col.f32.bf16.bf16.f32 "
        "{%0,%1,%2,%3},{%4,%5,%6,%7},{%8,%9},{%0,%1,%2,%3};"
        : "+f"(c[0]), "+f"(c[1]), "+f"(c[2]), "+f"(c[3])
        : "r"(a[0]), "r"(a[1]), "r"(a[2]), "r"(a[3]), "r"(b[0]), "r"(b[1]));
}

// ---------------------------------------------------------------------------
// Fused fp32 -> bf16 hi/lo split for x, W1, W2 in one launch
// ---------------------------------------------------------------------------
__global__ void split_all_kernel(const float* __restrict__ x,
                                 const float* __restrict__ W1,
                                 const float* __restrict__ W2, int nx4)
{
    constexpr int W1_4 = IND * D1 / 4;
    constexpr int W2_4 = D1 * D2 / 4;
    const int i = blockIdx.x * blockDim.x + threadIdx.x;

    const float* src;
    __nv_bfloat16 *hi, *lo;
    int idx;
    if (i < nx4)                  { src = x;  hi = g_xh;  lo = g_xl;  idx = i; }
    else if (i < nx4 + W1_4)      { src = W1; hi = g_w1h; lo = g_w1l; idx = i - nx4; }
    else if (i < nx4 + W1_4 + W2_4){ src = W2; hi = g_w2h; lo = g_w2l; idx = i - nx4 - W1_4; }
    else return;

    const float4 v = reinterpret_cast<const float4*>(src)[idx];
    float vv[4] = {v.x, v.y, v.z, v.w};
    __nv_bfloat16 h[4], l[4];
#pragma unroll
    for (int q = 0; q < 4; q++) {
        h[q] = __float2bfloat16(vv[q]);
        l[q] = __float2bfloat16(vv[q] - __bfloat162float(h[q]));
    }
    reinterpret_cast<__nv_bfloat162*>(hi)[2 * idx + 0] = __nv_bfloat162{h[0], h[1]};
    reinterpret_cast<__nv_bfloat162*>(hi)[2 * idx + 1] = __nv_bfloat162{h[2], h[3]};
    reinterpret_cast<__nv_bfloat162*>(lo)[2 * idx + 0] = __nv_bfloat162{l[0], l[1]};
    reinterpret_cast<__nv_bfloat162*>(lo)[2 * idx + 1] = __nv_bfloat162{l[2], l[3]};
}

// ---------------------------------------------------------------------------
// Zero: g_deg + the atomically-accumulated alpha2 dots
// ---------------------------------------------------------------------------
__global__ void zero_all_kernel(int n)
{
    const int i = blockIdx.x * blockDim.x + threadIdx.x;
    if (i < n) {
        g_deg[i] = 0;
        g_as2[i] = 0.f;
        g_ad2[i] = 0.f;
    }
}

// ---------------------------------------------------------------------------
// Tensor-core GEMM (bf16 3-term split) with fused alpha-dot epilogue.
// LAYER=1: C=g_h1 [M,256]; warp's 64-col span = one head -> full dot per
//          (row,head) inside one warp; quad-reduce + plain store to g_as1/ad1.
// LAYER=2: C=g_h2 [M,64]; two warps share a row -> atomicAdd into g_as2/ad2.
// ---------------------------------------------------------------------------
template <int LAYER>
__global__ void __launch_bounds__(256)
mma_gemm_kernel(int M, const float* __restrict__ avec_s,
                const float* __restrict__ avec_d)
{
    constexpr int K  = 256;
    constexpr int N  = (LAYER == 1) ? D1 : D2;
    constexpr int BN = (LAYER == 1) ? 128 : 64;
    constexpr int BM = 128;
    constexpr int BK = 32;
    constexpr int KP = BK + 8;
    constexpr int NP = BN + 8;
    constexpr int NT = BN / 16;
    constexpr int NBL = (BK * BN / 8) / 256;

    const __nv_bfloat16* __restrict__ Ah = (LAYER == 1) ? g_xh  : g_hrh;
    const __nv_bfloat16* __restrict__ Al = (LAYER == 1) ? g_xl  : g_hrl;
    const __nv_bfloat16* __restrict__ Bh = (LAYER == 1) ? g_w1h : g_w2h;
    const __nv_bfloat16* __restrict__ Bl = (LAYER == 1) ? g_w1l : g_w2l;
    float* __restrict__ C                = (LAYER == 1) ? g_h1  : g_h2;

    __shared__ __align__(16) __nv_bfloat16 sAh[BM][KP], sAl[BM][KP];
    __shared__ __align__(16) __nv_bfloat16 sBh[BK][NP], sBl[BK][NP];

    const int tid  = threadIdx.x;
    const int lane = tid & 31;
    const int wid  = tid >> 5;
    const int wm   = (wid & 3) * 32;
    const int wn   = (wid >> 2) * (BN / 2);
    const int brow = blockIdx.y * BM;
    const int bcol = blockIdx.x * BN;

    const int ar0 = tid >> 2, ar1 = (tid + 256) >> 2;
    const int ak  = (tid & 3) * 8;

    uint4 ua_h[2], ua_l[2], ub_h[NBL], ub_l[NBL];

    auto gload = [&](int k0) {
        const int rows[2] = {ar0, ar1};
#pragma unroll
        for (int s = 0; s < 2; s++) {
            const int gr = brow + rows[s];
            if (gr < M) {
                const size_t off = (size_t)gr * K + k0 + ak;
                ua_h[s] = *reinterpret_cast<const uint4*>(Ah + off);
                ua_l[s] = *reinterpret_cast<const uint4*>(Al + off);
            } else {
                ua_h[s] = make_uint4(0, 0, 0, 0);
                ua_l[s] = make_uint4(0, 0, 0, 0);
            }
        }
#pragma unroll
        for (int s = 0; s < NBL; s++) {
            const int slot = tid + s * 256;
            const int kr = slot / (BN / 8);
            const int nc = (slot % (BN / 8)) * 8;
            const size_t off = (size_t)(k0 + kr) * N + bcol + nc;
            ub_h[s] = *reinterpret_cast<const uint4*>(Bh + off);
            ub_l[s] = *reinterpret_cast<const uint4*>(Bl + off);
        }
    };
    auto sstore = [&]() {
        const int rows[2] = {ar0, ar1};
#pragma unroll
        for (int s = 0; s < 2; s++) {
            *reinterpret_cast<uint4*>(&sAh[rows[s]][ak]) = ua_h[s];
            *reinterpret_cast<uint4*>(&sAl[rows[s]][ak]) = ua_l[s];
        }
#pragma unroll
        for (int s = 0; s < NBL; s++) {
            const int slot = tid + s * 256;
            const int kr = slot / (BN / 8);
            const int nc = (slot % (BN / 8)) * 8;
            *reinterpret_cast<uint4*>(&sBh[kr][nc]) = ub_h[s];
            *reinterpret_cast<uint4*>(&sBl[kr][nc]) = ub_l[s];
        }
    };

    float c[2][NT][4];
#pragma unroll
    for (int i = 0; i < 2; i++)
#pragma unroll
        for (int j = 0; j < NT; j++)
#pragma unroll
            for (int q = 0; q < 4; q++) c[i][j][q] = 0.f;

    gload(0);
    sstore();
    __syncthreads();

    constexpr int NKT = K / BK;
    for (int kt = 0; kt < NKT; kt++) {
        if (kt + 1 < NKT) gload((kt + 1) * BK);

#pragma unroll
        for (int ks = 0; ks < 2; ks++) {
            const int k16 = ks * 16;
            uint32_t fa_h[2][4], fa_l[2][4];
#pragma unroll
            for (int i = 0; i < 2; i++) {
                const int row = wm + i * 16 + (lane & 15);
                const int col = k16 + 8 * (lane >> 4);
                ldsm4(fa_h[i], sptr(&sAh[row][col]));
                ldsm4(fa_l[i], sptr(&sAl[row][col]));
            }
            uint32_t fb_h[NT][2], fb_l[NT][2];
#pragma unroll
            for (int j = 0; j < NT / 2; j++) {
                const int rr = k16 + (lane & 15);
                const int cc = wn + j * 16 + 8 * (lane >> 4);
                uint32_t t[4];
                ldsm4t(t, sptr(&sBh[rr][cc]));
                fb_h[2 * j][0] = t[0]; fb_h[2 * j][1] = t[1];
                fb_h[2 * j + 1][0] = t[2]; fb_h[2 * j + 1][1] = t[3];
                ldsm4t(t, sptr(&sBl[rr][cc]));
                fb_l[2 * j][0] = t[0]; fb_l[2 * j][1] = t[1];
                fb_l[2 * j + 1][0] = t[2]; fb_l[2 * j + 1][1] = t[3];
            }
#pragma unroll
            for (int i = 0; i < 2; i++)
#pragma unroll
                for (int j = 0; j < NT; j++) {
                    mma16816(c[i][j], fa_h[i], fb_h[j]);
                    mma16816(c[i][j], fa_h[i], fb_l[j]);
                    mma16816(c[i][j], fa_l[i], fb_h[j]);
                }
        }

        __syncthreads();
        if (kt + 1 < NKT) {
            sstore();
            __syncthreads();
        }
    }

    // ---- epilogue: store C + fused alpha dots ----
#pragma unroll
    for (int i = 0; i < 2; i++) {
        float s0 = 0.f, s1 = 0.f, d0 = 0.f, d1 = 0.f;
#pragma unroll
        for (int j = 0; j < NT; j++) {
            const int col = bcol + wn + j * 8 + (lane & 3) * 2;
            const float a0 = __ldg(avec_s + col), a1 = __ldg(avec_s + col + 1);
            const float b0 = __ldg(avec_d + col), b1 = __ldg(avec_d + col + 1);
            s0 += c[i][j][0] * a0 + c[i][j][1] * a1;
            s1 += c[i][j][2] * a0 + c[i][j][3] * a1;
            d0 += c[i][j][0] * b0 + c[i][j][1] * b1;
            d1 += c[i][j][2] * b0 + c[i][j][3] * b1;

            const int r   = brow + wm + i * 16 + (lane >> 2);
            if (r < M)
                *reinterpret_cast<float2*>(C + (size_t)r * N + col) =
                    make_float2(c[i][j][0], c[i][j][1]);
            if (r + 8 < M)
                *reinterpret_cast<float2*>(C + (size_t)(r + 8) * N + col) =
                    make_float2(c[i][j][2], c[i][j][3]);
        }
        // quad reduce (lanes differing in bits 0..1 share the same row)
#pragma unroll
        for (int off = 1; off <= 2; off <<= 1) {
            s0 += __shfl_xor_sync(0xffffffffu, s0, off);
            s1 += __shfl_xor_sync(0xffffffffu, s1, off);
            d0 += __shfl_xor_sync(0xffffffffu, d0, off);
            d1 += __shfl_xor_sync(0xffffffffu, d1, off);
        }
        if ((lane & 3) == 0) {
            const int r = brow + wm + i * 16 + (lane >> 2);
            if (LAYER == 1) {
                const int head = (bcol + wn) >> 6;   // warp spans one head
                if (r < M)     { g_as1[r * 4 + head] = s0; g_ad1[r * 4 + head] = d0; }
                if (r + 8 < M) { g_as1[(r + 8) * 4 + head] = s1; g_ad1[(r + 8) * 4 + head] = d1; }
            } else {
                if (r < M)     { atomicAdd(&g_as2[r], s0); atomicAdd(&g_ad2[r], d0); }
                if (r + 8 < M) { atomicAdd(&g_as2[r + 8], s1); atomicAdd(&g_ad2[r + 8], d1); }
            }
        }
    }
}

// ---------------------------------------------------------------------------
// CSR build
// ---------------------------------------------------------------------------
__global__ void hist_kernel(const int* __restrict__ ei, int E, int n)
{
    const int i = blockIdx.x * blockDim.x + threadIdx.x;
    const int tot = E + n;
    if (i >= tot) return;
    const int d = (i < E) ? ei[E + i] : (i - E);
    if ((unsigned)d < (unsigned)n)
        atomicAdd(&g_deg[d], 1);
}

__global__ void scan1_kernel(int n)
{
    __shared__ int smem[1024];
    const int tid = threadIdx.x;
    const int i = blockIdx.x * 1024 + tid;
    const int v = (i < n) ? g_deg[i] : 0;
    int x = v;
#pragma unroll
    for (int off = 1; off < 1024; off <<= 1) {
        smem[tid] = x;
        __syncthreads();
        if (tid >= off) x += smem[tid - off];
        __syncthreads();
    }
    if (i < n) g_row[i] = x - v;
    if (tid == 1023) g_bsum[blockIdx.x] = x;
}

__global__ void scan2_kernel(int nb, int n)
{
    __shared__ int sm[64];
    const int tid = threadIdx.x;
    const int v = (tid < nb) ? g_bsum[tid] : 0;
    int x = v;
#pragma unroll
    for (int off = 1; off < 64; off <<= 1) {
        sm[tid] = x;
        __syncthreads();
        if (tid >= off) x += sm[tid - off];
        __syncthreads();
    }
    if (tid < nb) g_boff[tid] = x - v;
    if (tid == 63) g_row[n] = x;
}

__global__ void scan3_kernel(int n)
{
    const int i = blockIdx.x * blockDim.x + threadIdx.x;
    if (i >= n) return;
    const int v = g_row[i] + g_boff[i >> 10];
    g_row[i] = v;
    g_cur[i] = v;
}

__global__ void scatter_kernel(const int* __restrict__ ei, int E, int n)
{
    const int i = blockIdx.x * blockDim.x + threadIdx.x;
    const int tot = E + n;
    if (i >= tot) return;
    int s, d;
    if (i < E) {
        s = ei[i];
        d = ei[E + i];
    } else {
        s = d = i - E;
    }
    if ((unsigned)d < (unsigned)n && (unsigned)s < (unsigned)n) {
        const int pos = atomicAdd(&g_cur[d], 1);
        if ((unsigned)pos < (unsigned)ETOT)
            g_csr[pos] = s;
    }
}

// ---------------------------------------------------------------------------
// GAT aggregation, warp-per-destination.
// 2 passes now (no max subtraction: exp(e)/sum(exp(e)) is exact):
//   pass A: segment sum of exp (lane-parallel)
//   pass B: chunked weighted gather-accumulate
// ---------------------------------------------------------------------------
#define AGG_WARPS 8

template <int HEADS, int RP, bool L1>
__global__ void __launch_bounds__(AGG_WARPS * 32)
agg_kernel(const float* __restrict__ bias,
           float* __restrict__ out_ext, int n)
{
    constexpr int D = RP * 32;
    const float* __restrict__ h  = L1 ? g_h1  : g_h2;
    const float* __restrict__ as = L1 ? g_as1 : g_as2;
    const float* __restrict__ ad = L1 ? g_ad1 : g_ad2;

    __shared__ int   s_src[AGG_WARPS][32];
    __shared__ float s_w[AGG_WARPS][32][HEADS];

    const int warp  = (blockIdx.x * blockDim.x + threadIdx.x) >> 5;
    const int wslot = threadIdx.x >> 5;
    const int lane  = threadIdx.x & 31;
    if (warp >= n) return;

    const int start = g_row[warp];
    const int end   = g_row[warp + 1];

    float adv[HEADS];
#pragma unroll
    for (int hh = 0; hh < HEADS; hh++) adv[hh] = ad[warp * HEADS + hh];

    // ---- pass A: sum of exp ----
    float ssum[HEADS];
#pragma unroll
    for (int hh = 0; hh < HEADS; hh++) ssum[hh] = 0.f;
    for (int i = start + lane; i < end; i += 32) {
        const int s = g_csr[i];
#pragma unroll
        for (int hh = 0; hh < HEADS; hh++) {
            float e = as[s * HEADS + hh] + adv[hh];
            e = (e >= 0.f) ? e : NEG_SLOPE * e;
            ssum[hh] += __expf(e);
        }
    }
#pragma unroll
    for (int hh = 0; hh < HEADS; hh++) {
#pragma unroll
        for (int off = 16; off > 0; off >>= 1)
            ssum[hh] += __shfl_xor_sync(0xffffffffu, ssum[hh], off);
    }
    float inv[HEADS];
#pragma unroll
    for (int hh = 0; hh < HEADS; hh++) inv[hh] = 1.0f / ssum[hh];

    // ---- pass B: chunked weighted gather-accumulate ----
    const int head = (lane * RP) >> 6;
    float acc[RP];
#pragma unroll
    for (int r = 0; r < RP; r++) acc[r] = 0.f;

    for (int base = start; base < end; base += 32) {
        const int cnt = min(32, end - base);
        const int i = base + lane;
        if (lane < cnt) {
            const int s = g_csr[i];
            s_src[wslot][lane] = s;
#pragma unroll
            for (int hh = 0; hh < HEADS; hh++) {
                float e = as[s * HEADS + hh] + adv[hh];
                e = (e >= 0.f) ? e : NEG_SLOPE * e;
                s_w[wslot][lane][hh] = __expf(e) * inv[hh];
            }
        }
        __syncwarp();

#pragma unroll 2
        for (int j = 0; j < cnt; j++) {
            const int s   = s_src[wslot][j];
            const float w = s_w[wslot][j][head];
            const float* rowp = h + (size_t)s * D + lane * RP;
            if constexpr (RP == 8) {
                const float4 v0 = *reinterpret_cast<const float4*>(rowp);
                const float4 v1 = *reinterpret_cast<const float4*>(rowp + 4);
                acc[0] += w * v0.x; acc[1] += w * v0.y;
                acc[2] += w * v0.z; acc[3] += w * v0.w;
                acc[4] += w * v1.x; acc[5] += w * v1.y;
                acc[6] += w * v1.z; acc[7] += w * v1.w;
            } else {
                const float2 v0 = *reinterpret_cast<const float2*>(rowp);
                acc[0] += w * v0.x; acc[1] += w * v0.y;
            }
        }
        __syncwarp();
    }

    // ---- epilogue ----
#pragma unroll
    for (int r = 0; r < RP; r++) {
        float v = acc[r] + bias[lane * RP + r];
        if (L1) v = fmaxf(v, 0.f);
        acc[r] = v;
    }
    if constexpr (L1) {
        __nv_bfloat16 hb[RP], lb[RP];
#pragma unroll
        for (int r = 0; r < RP; r++) {
            hb[r] = __float2bfloat16(acc[r]);
            lb[r] = __float2bfloat16(acc[r] - __bfloat162float(hb[r]));
        }
        const size_t o = (size_t)warp * D + lane * RP;
        __nv_bfloat162* oh = reinterpret_cast<__nv_bfloat162*>(g_hrh + o);
        __nv_bfloat162* ol = reinterpret_cast<__nv_bfloat162*>(g_hrl + o);
#pragma unroll
        for (int r = 0; r < RP / 2; r++) {
            oh[r] = __nv_bfloat162{hb[2 * r], hb[2 * r + 1]};
            ol[r] = __nv_bfloat162{lb[2 * r], lb[2 * r + 1]};
        }
    } else {
        float* op = out_ext + (size_t)warp * D + lane * RP;
        *reinterpret_cast<float2*>(op) = make_float2(acc[0], acc[1]);
    }
}

// ---------------------------------------------------------------------------
// Launch — kernel launches ONLY.  Order puts GEMM1 at captured index 3.
// ---------------------------------------------------------------------------
extern "C" void kernel_launch(void* const* d_in, const int* in_sizes, int n_in,
                              void* d_out, int out_size)
{
    const float* x      = (const float*)d_in[0];
    const int*   ei     = (const int*)d_in[1];   // int32 (JAX x64 disabled)
    const float* W1     = (const float*)d_in[2];
    const float* a_src1 = (const float*)d_in[3];
    const float* a_dst1 = (const float*)d_in[4];
    const float* b1     = (const float*)d_in[5];
    const float* W2     = (const float*)d_in[6];
    const float* a_src2 = (const float*)d_in[7];
    const float* a_dst2 = (const float*)d_in[8];
    const float* b2     = (const float*)d_in[9];
    float*       out    = (float*)d_out;

    const int n = in_sizes[0] / IND;      // 50000
    const int E = in_sizes[1] / 2;        // 800000
    const int tot = E + n;

    const int nb256 = (n + 255) / 256;
    const int eb256 = (tot + 255) / 256;
    const int nscan = (n + 1023) / 1024;

    // 0: fused bf16 splits
    {
        const int nx4 = (n * IND) / 4;
        const int tot4 = nx4 + IND * D1 / 4 + D1 * D2 / 4;
        split_all_kernel<<<(tot4 + 255) / 256, 256>>>(x, W1, W2, nx4);
    }
    // 1: zero deg + alpha2 accumulators
    zero_all_kernel<<<nb256, 256>>>(n);
    // 2: histogram
    hist_kernel<<<eb256, 256>>>(ei, E, n);
    // 3: GEMM1 (+ fused alpha1)  <- ncu captures this index
    {
        dim3 grid(D1 / 128, (n + 127) / 128);
        mma_gemm_kernel<1><<<grid, 256>>>(n, a_src1, a_dst1);
    }
    // 4-7: scan + scatter
    scan1_kernel<<<nscan, 1024>>>(n);
    scan2_kernel<<<1, 64>>>(nscan, n);
    scan3_kernel<<<nb256, 256>>>(n);
    scatter_kernel<<<eb256, 256>>>(ei, E, n);
    // 8: aggregation layer 1
    {
        const int grid = (n + AGG_WARPS - 1) / AGG_WARPS;
        agg_kernel<NHEADS, 8, true><<<grid, AGG_WARPS * 32>>>(b1, nullptr, n);
    }
    // 9: GEMM2 (+ fused alpha2)
    {
        dim3 grid(D2 / 64, (n + 127) / 128);
        mma_gemm_kernel<2><<<grid, 256>>>(n, a_src2, a_dst2);
    }
    // 10: aggregation layer 2 -> out
    {
        const int grid = (n + AGG_WARPS - 1) / AGG_WARPS;
        agg_kernel<1, 2, false><<<grid, AGG_WARPS * 32>>>(b2, out, n);
    }
}

// round 10
// speedup vs baseline: 1.8710x; 1.0180x over previous
#include <cuda_runtime.h>
#include <cuda_bf16.h>
#include <cstdint>
#include <cmath>

// Problem constants (match reference_code)
#define NN     50000
#define EE     800000
#define ETOT   (NN + EE)
#define IND    256
#define HIDD   64
#define NHEADS 4
#define D1     256
#define D2     64
#define NEG_SLOPE 0.2f

// ---------------------------------------------------------------------------
// Scratch
// ---------------------------------------------------------------------------
__device__ __align__(16) float g_h1[(size_t)NN * D1];
__device__ __align__(16) float g_h2[(size_t)NN * D2];
__device__ __align__(16) __nv_bfloat16 g_xh[(size_t)NN * IND];
__device__ __align__(16) __nv_bfloat16 g_xl[(size_t)NN * IND];
__device__ __align__(16) __nv_bfloat16 g_w1h[IND * D1];
__device__ __align__(16) __nv_bfloat16 g_w1l[IND * D1];
__device__ __align__(16) __nv_bfloat16 g_w2h[D1 * D2];
__device__ __align__(16) __nv_bfloat16 g_w2l[D1 * D2];
__device__ __align__(16) __nv_bfloat16 g_hrh[(size_t)NN * D1];
__device__ __align__(16) __nv_bfloat16 g_hrl[(size_t)NN * D1];
__device__ __align__(16) float g_as1[NN * NHEADS];
__device__ __align__(16) float g_ad1[NN * NHEADS];
__device__ __align__(16) float g_as2[NN];
__device__ __align__(16) float g_ad2[NN];
__device__ int   g_deg[NN];
__device__ int   g_row[NN + 1];
__device__ int   g_cur[NN];
__device__ int   g_csr[ETOT];
__device__ int   g_bsum[64];
__device__ int   g_boff[64];

// ---------------------------------------------------------------------------
// PTX helpers
// ---------------------------------------------------------------------------
__device__ __forceinline__ uint32_t sptr(const void* p) {
    return (uint32_t)__cvta_generic_to_shared(p);
}
__device__ __forceinline__ void ldsm4(uint32_t* r, uint32_t a) {
    asm volatile("ldmatrix.sync.aligned.m8n8.x4.shared.b16 {%0,%1,%2,%3}, [%4];"
                 : "=r"(r[0]), "=r"(r[1]), "=r"(r[2]), "=r"(r[3]) : "r"(a));
}
__device__ __forceinline__ void ldsm4t(uint32_t* r, uint32_t a) {
    asm volatile("ldmatrix.sync.aligned.m8n8.x4.trans.shared.b16 {%0,%1,%2,%3}, [%4];"
                 : "=r"(r[0]), "=r"(r[1]), "=r"(r[2]), "=r"(r[3]) : "r"(a));
}
__device__ __forceinline__ void mma16816(float* c, const uint32_t* a, const uint32_t* b) {
    asm volatile(
        "mma.sync.aligned.m16n8k16.row.col.f32.bf16.bf16.f32 "
        "{%0,%1,%2,%3},{%4,%5,%6,%7},{%8,%9},{%0,%1,%2,%3};"
        : "+f"(c[0]), "+f"(c[1]), "+f"(c[2]), "+f"(c[3])
        : "r"(a[0]), "r"(a[1]), "r"(a[2]), "r"(a[3]), "r"(b[0]), "r"(b[1]));
}

// ---------------------------------------------------------------------------
// Fused fp32 -> bf16 hi/lo split for x, W1, W2 in one launch
// ---------------------------------------------------------------------------
__global__ void split_all_kernel(const float* __restrict__ x,
                                 const float* __restrict__ W1,
                                 const float* __restrict__ W2, int nx4)
{
    constexpr int W1_4 = IND * D1 / 4;
    constexpr int W2_4 = D1 * D2 / 4;
    const int i = blockIdx.x * blockDim.x + threadIdx.x;

    const float* src;
    __nv_bfloat16 *hi, *lo;
    int idx;
    if (i < nx4)                  { src = x;  hi = g_xh;  lo = g_xl;  idx = i; }
    else if (i < nx4 + W1_4)      { src = W1; hi = g_w1h; lo = g_w1l; idx = i - nx4; }
    else if (i < nx4 + W1_4 + W2_4){ src = W2; hi = g_w2h; lo = g_w2l; idx = i - nx4 - W1_4; }
    else return;

    const float4 v = reinterpret_cast<const float4*>(src)[idx];
    float vv[4] = {v.x, v.y, v.z, v.w};
    __nv_bfloat16 h[4], l[4];
#pragma unroll
    for (int q = 0; q < 4; q++) {
        h[q] = __float2bfloat16(vv[q]);
        l[q] = __float2bfloat16(vv[q] - __bfloat162float(h[q]));
    }
    reinterpret_cast<__nv_bfloat162*>(hi)[2 * idx + 0] = __nv_bfloat162{h[0], h[1]};
    reinterpret_cast<__nv_bfloat162*>(hi)[2 * idx + 1] = __nv_bfloat162{h[2], h[3]};
    reinterpret_cast<__nv_bfloat162*>(lo)[2 * idx + 0] = __nv_bfloat162{l[0], l[1]};
    reinterpret_cast<__nv_bfloat162*>(lo)[2 * idx + 1] = __nv_bfloat162{l[2], l[3]};
}

// ---------------------------------------------------------------------------
// Zero: g_deg + all atomically-accumulated alpha dots
// ---------------------------------------------------------------------------
__global__ void zero_all_kernel(int n)
{
    const int i = blockIdx.x * blockDim.x + threadIdx.x;
    if (i < n) {
        g_deg[i] = 0;
        g_as2[i] = 0.f;
        g_ad2[i] = 0.f;
    }
    if (i < n * NHEADS) {
        g_as1[i] = 0.f;
        g_ad1[i] = 0.f;
    }
}

// ---------------------------------------------------------------------------
// Tensor-core GEMM (bf16 3-term split), 128x64 tile, 2 CTAs/SM, fused alpha.
// Warp layout: 8 warps as 4m x 2n, warp tile 32x32.
// Alpha dots: quad-reduce partial (32-col) sums, atomicAdd into g_as*/g_ad*.
// ---------------------------------------------------------------------------
template <int LAYER>
__global__ void __launch_bounds__(256, 2)
mma_gemm_kernel(int M, const float* __restrict__ avec_s,
                const float* __restrict__ avec_d)
{
    constexpr int K  = 256;
    constexpr int N  = (LAYER == 1) ? D1 : D2;
    constexpr int BN = 64;
    constexpr int BM = 128;
    constexpr int BK = 32;
    constexpr int KP = BK + 8;
    constexpr int NP = BN + 8;
    constexpr int NT = 4;            // 32-wide warp tile = 4 n8 frags

    const __nv_bfloat16* __restrict__ Ah = (LAYER == 1) ? g_xh  : g_hrh;
    const __nv_bfloat16* __restrict__ Al = (LAYER == 1) ? g_xl  : g_hrl;
    const __nv_bfloat16* __restrict__ Bh = (LAYER == 1) ? g_w1h : g_w2h;
    const __nv_bfloat16* __restrict__ Bl = (LAYER == 1) ? g_w1l : g_w2l;
    float* __restrict__ C                = (LAYER == 1) ? g_h1  : g_h2;
    float* __restrict__ as_out           = (LAYER == 1) ? g_as1 : g_as2;
    float* __restrict__ ad_out           = (LAYER == 1) ? g_ad1 : g_ad2;

    __shared__ __align__(16) __nv_bfloat16 sAh[BM][KP], sAl[BM][KP];
    __shared__ __align__(16) __nv_bfloat16 sBh[BK][NP], sBl[BK][NP];

    const int tid  = threadIdx.x;
    const int lane = tid & 31;
    const int wid  = tid >> 5;
    const int wm   = (wid & 3) * 32;
    const int wn   = (wid >> 2) * 32;
    const int brow = blockIdx.y * BM;
    const int bcol = blockIdx.x * BN;

    // A loader: 128x32 tile = 512 uint4 slots, 2/thread
    const int ar0 = tid >> 2, ar1 = (tid + 256) >> 2;
    const int ak  = (tid & 3) * 8;
    // B loader: 32x64 tile = 256 uint4 slots, 1/thread
    const int bkr = tid >> 3;
    const int bnc = (tid & 7) * 8;

    uint4 ua_h[2], ua_l[2], ub_h, ub_l;

    auto gload = [&](int k0) {
        const int rows[2] = {ar0, ar1};
#pragma unroll
        for (int s = 0; s < 2; s++) {
            const int gr = brow + rows[s];
            if (gr < M) {
                const size_t off = (size_t)gr * K + k0 + ak;
                ua_h[s] = *reinterpret_cast<const uint4*>(Ah + off);
                ua_l[s] = *reinterpret_cast<const uint4*>(Al + off);
            } else {
                ua_h[s] = make_uint4(0, 0, 0, 0);
                ua_l[s] = make_uint4(0, 0, 0, 0);
            }
        }
        const size_t off = (size_t)(k0 + bkr) * N + bcol + bnc;
        ub_h = *reinterpret_cast<const uint4*>(Bh + off);
        ub_l = *reinterpret_cast<const uint4*>(Bl + off);
    };
    auto sstore = [&]() {
        const int rows[2] = {ar0, ar1};
#pragma unroll
        for (int s = 0; s < 2; s++) {
            *reinterpret_cast<uint4*>(&sAh[rows[s]][ak]) = ua_h[s];
            *reinterpret_cast<uint4*>(&sAl[rows[s]][ak]) = ua_l[s];
        }
        *reinterpret_cast<uint4*>(&sBh[bkr][bnc]) = ub_h;
        *reinterpret_cast<uint4*>(&sBl[bkr][bnc]) = ub_l;
    };

    float c[2][NT][4];
#pragma unroll
    for (int i = 0; i < 2; i++)
#pragma unroll
        for (int j = 0; j < NT; j++)
#pragma unroll
            for (int q = 0; q < 4; q++) c[i][j][q] = 0.f;

    gload(0);
    sstore();
    __syncthreads();

    constexpr int NKT = K / BK;   // 8
    for (int kt = 0; kt < NKT; kt++) {
        if (kt + 1 < NKT) gload((kt + 1) * BK);

#pragma unroll
        for (int ks = 0; ks < 2; ks++) {
            const int k16 = ks * 16;
            uint32_t fa_h[2][4], fa_l[2][4];
#pragma unroll
            for (int i = 0; i < 2; i++) {
                const int row = wm + i * 16 + (lane & 15);
                const int col = k16 + 8 * (lane >> 4);
                ldsm4(fa_h[i], sptr(&sAh[row][col]));
                ldsm4(fa_l[i], sptr(&sAl[row][col]));
            }
            uint32_t fb_h[NT][2], fb_l[NT][2];
#pragma unroll
            for (int j = 0; j < NT / 2; j++) {
                const int rr = k16 + (lane & 15);
                const int cc = wn + j * 16 + 8 * (lane >> 4);
                uint32_t t[4];
                ldsm4t(t, sptr(&sBh[rr][cc]));
                fb_h[2 * j][0] = t[0]; fb_h[2 * j][1] = t[1];
                fb_h[2 * j + 1][0] = t[2]; fb_h[2 * j + 1][1] = t[3];
                ldsm4t(t, sptr(&sBl[rr][cc]));
                fb_l[2 * j][0] = t[0]; fb_l[2 * j][1] = t[1];
                fb_l[2 * j + 1][0] = t[2]; fb_l[2 * j + 1][1] = t[3];
            }
#pragma unroll
            for (int i = 0; i < 2; i++)
#pragma unroll
                for (int j = 0; j < NT; j++) {
                    mma16816(c[i][j], fa_h[i], fb_h[j]);
                    mma16816(c[i][j], fa_h[i], fb_l[j]);
                    mma16816(c[i][j], fa_l[i], fb_h[j]);
                }
        }

        __syncthreads();
        if (kt + 1 < NKT) {
            sstore();
            __syncthreads();
        }
    }

    // ---- epilogue: store C + fused (partial) alpha dots ----
    const int head = (LAYER == 1) ? (bcol >> 6) : 0;
#pragma unroll
    for (int i = 0; i < 2; i++) {
        float s0 = 0.f, s1 = 0.f, d0 = 0.f, d1 = 0.f;
#pragma unroll
        for (int j = 0; j < NT; j++) {
            const int col = bcol + wn + j * 8 + (lane & 3) * 2;
            const float a0 = __ldg(avec_s + col), a1 = __ldg(avec_s + col + 1);
            const float b0 = __ldg(avec_d + col), b1 = __ldg(avec_d + col + 1);
            s0 += c[i][j][0] * a0 + c[i][j][1] * a1;
            s1 += c[i][j][2] * a0 + c[i][j][3] * a1;
            d0 += c[i][j][0] * b0 + c[i][j][1] * b1;
            d1 += c[i][j][2] * b0 + c[i][j][3] * b1;

            const int r = brow + wm + i * 16 + (lane >> 2);
            if (r < M)
                *reinterpret_cast<float2*>(C + (size_t)r * N + col) =
                    make_float2(c[i][j][0], c[i][j][1]);
            if (r + 8 < M)
                *reinterpret_cast<float2*>(C + (size_t)(r + 8) * N + col) =
                    make_float2(c[i][j][2], c[i][j][3]);
        }
#pragma unroll
        for (int off = 1; off <= 2; off <<= 1) {
            s0 += __shfl_xor_sync(0xffffffffu, s0, off);
            s1 += __shfl_xor_sync(0xffffffffu, s1, off);
            d0 += __shfl_xor_sync(0xffffffffu, d0, off);
            d1 += __shfl_xor_sync(0xffffffffu, d1, off);
        }
        if ((lane & 3) == 0) {
            const int r = brow + wm + i * 16 + (lane >> 2);
            const int stride = (LAYER == 1) ? NHEADS : 1;
            if (r < M) {
                atomicAdd(&as_out[r * stride + head], s0);
                atomicAdd(&ad_out[r * stride + head], d0);
            }
            if (r + 8 < M) {
                atomicAdd(&as_out[(r + 8) * stride + head], s1);
                atomicAdd(&ad_out[(r + 8) * stride + head], d1);
            }
        }
    }
}

// ---------------------------------------------------------------------------
// CSR build
// ---------------------------------------------------------------------------
__global__ void hist_kernel(const int* __restrict__ ei, int E, int n)
{
    const int i = blockIdx.x * blockDim.x + threadIdx.x;
    const int tot = E + n;
    if (i >= tot) return;
    const int d = (i < E) ? ei[E + i] : (i - E);
    if ((unsigned)d < (unsigned)n)
        atomicAdd(&g_deg[d], 1);
}

__global__ void scan1_kernel(int n)
{
    __shared__ int smem[1024];
    const int tid = threadIdx.x;
    const int i = blockIdx.x * 1024 + tid;
    const int v = (i < n) ? g_deg[i] : 0;
    int x = v;
#pragma unroll
    for (int off = 1; off < 1024; off <<= 1) {
        smem[tid] = x;
        __syncthreads();
        if (tid >= off) x += smem[tid - off];
        __syncthreads();
    }
    if (i < n) g_row[i] = x - v;
    if (tid == 1023) g_bsum[blockIdx.x] = x;
}

__global__ void scan2_kernel(int nb, int n)
{
    __shared__ int sm[64];
    const int tid = threadIdx.x;
    const int v = (tid < nb) ? g_bsum[tid] : 0;
    int x = v;
#pragma unroll
    for (int off = 1; off < 64; off <<= 1) {
        sm[tid] = x;
        __syncthreads();
        if (tid >= off) x += sm[tid - off];
        __syncthreads();
    }
    if (tid < nb) g_boff[tid] = x - v;
    if (tid == 63) g_row[n] = x;
}

__global__ void scan3_kernel(int n)
{
    const int i = blockIdx.x * blockDim.x + threadIdx.x;
    if (i >= n) return;
    const int v = g_row[i] + g_boff[i >> 10];
    g_row[i] = v;
    g_cur[i] = v;
}

__global__ void scatter_kernel(const int* __restrict__ ei, int E, int n)
{
    const int i = blockIdx.x * blockDim.x + threadIdx.x;
    const int tot = E + n;
    if (i >= tot) return;
    int s, d;
    if (i < E) {
        s = ei[i];
        d = ei[E + i];
    } else {
        s = d = i - E;
    }
    if ((unsigned)d < (unsigned)n && (unsigned)s < (unsigned)n) {
        const int pos = atomicAdd(&g_cur[d], 1);
        if ((unsigned)pos < (unsigned)ETOT)
            g_csr[pos] = s;
    }
}

// ---------------------------------------------------------------------------
// GAT aggregation, warp-per-destination (2-pass softmax, chunked gather).
// ---------------------------------------------------------------------------
#define AGG_WARPS 8

template <int HEADS, int RP, bool L1>
__global__ void __launch_bounds__(AGG_WARPS * 32)
agg_kernel(const float* __restrict__ bias,
           float* __restrict__ out_ext, int n)
{
    constexpr int D = RP * 32;
    const float* __restrict__ h  = L1 ? g_h1  : g_h2;
    const float* __restrict__ as = L1 ? g_as1 : g_as2;
    const float* __restrict__ ad = L1 ? g_ad1 : g_ad2;

    __shared__ int   s_src[AGG_WARPS][32];
    __shared__ float s_w[AGG_WARPS][32][HEADS];

    const int warp  = (blockIdx.x * blockDim.x + threadIdx.x) >> 5;
    const int wslot = threadIdx.x >> 5;
    const int lane  = threadIdx.x & 31;
    if (warp >= n) return;

    const int start = g_row[warp];
    const int end   = g_row[warp + 1];

    float adv[HEADS];
#pragma unroll
    for (int hh = 0; hh < HEADS; hh++) adv[hh] = ad[warp * HEADS + hh];

    // ---- pass A: sum of exp ----
    float ssum[HEADS];
#pragma unroll
    for (int hh = 0; hh < HEADS; hh++) ssum[hh] = 0.f;
    for (int i = start + lane; i < end; i += 32) {
        const int s = g_csr[i];
#pragma unroll
        for (int hh = 0; hh < HEADS; hh++) {
            float e = as[s * HEADS + hh] + adv[hh];
            e = (e >= 0.f) ? e : NEG_SLOPE * e;
            ssum[hh] += __expf(e);
        }
    }
#pragma unroll
    for (int hh = 0; hh < HEADS; hh++) {
#pragma unroll
        for (int off = 16; off > 0; off >>= 1)
            ssum[hh] += __shfl_xor_sync(0xffffffffu, ssum[hh], off);
    }
    float inv[HEADS];
#pragma unroll
    for (int hh = 0; hh < HEADS; hh++) inv[hh] = 1.0f / ssum[hh];

    // ---- pass B: chunked weighted gather-accumulate ----
    const int head = (lane * RP) >> 6;
    float acc[RP];
#pragma unroll
    for (int r = 0; r < RP; r++) acc[r] = 0.f;

    for (int base = start; base < end; base += 32) {
        const int cnt = min(32, end - base);
        const int i = base + lane;
        if (lane < cnt) {
            const int s = g_csr[i];
            s_src[wslot][lane] = s;
#pragma unroll
            for (int hh = 0; hh < HEADS; hh++) {
                float e = as[s * HEADS + hh] + adv[hh];
                e = (e >= 0.f) ? e : NEG_SLOPE * e;
                s_w[wslot][lane][hh] = __expf(e) * inv[hh];
            }
        }
        __syncwarp();

#pragma unroll 2
        for (int j = 0; j < cnt; j++) {
            const int s   = s_src[wslot][j];
            const float w = s_w[wslot][j][head];
            const float* rowp = h + (size_t)s * D + lane * RP;
            if constexpr (RP == 8) {
                const float4 v0 = *reinterpret_cast<const float4*>(rowp);
                const float4 v1 = *reinterpret_cast<const float4*>(rowp + 4);
                acc[0] += w * v0.x; acc[1] += w * v0.y;
                acc[2] += w * v0.z; acc[3] += w * v0.w;
                acc[4] += w * v1.x; acc[5] += w * v1.y;
                acc[6] += w * v1.z; acc[7] += w * v1.w;
            } else {
                const float2 v0 = *reinterpret_cast<const float2*>(rowp);
                acc[0] += w * v0.x; acc[1] += w * v0.y;
            }
        }
        __syncwarp();
    }

    // ---- epilogue ----
#pragma unroll
    for (int r = 0; r < RP; r++) {
        float v = acc[r] + bias[lane * RP + r];
        if (L1) v = fmaxf(v, 0.f);
        acc[r] = v;
    }
    if constexpr (L1) {
        __nv_bfloat16 hb[RP], lb[RP];
#pragma unroll
        for (int r = 0; r < RP; r++) {
            hb[r] = __float2bfloat16(acc[r]);
            lb[r] = __float2bfloat16(acc[r] - __bfloat162float(hb[r]));
        }
        const size_t o = (size_t)warp * D + lane * RP;
        __nv_bfloat162* oh = reinterpret_cast<__nv_bfloat162*>(g_hrh + o);
        __nv_bfloat162* ol = reinterpret_cast<__nv_bfloat162*>(g_hrl + o);
#pragma unroll
        for (int r = 0; r < RP / 2; r++) {
            oh[r] = __nv_bfloat162{hb[2 * r], hb[2 * r + 1]};
            ol[r] = __nv_bfloat162{lb[2 * r], lb[2 * r + 1]};
        }
    } else {
        float* op = out_ext + (size_t)warp * D + lane * RP;
        *reinterpret_cast<float2*>(op) = make_float2(acc[0], acc[1]);
    }
}

// ---------------------------------------------------------------------------
// Launch — kernel launches ONLY.  GEMM1 at captured index 3.
// ---------------------------------------------------------------------------
extern "C" void kernel_launch(void* const* d_in, const int* in_sizes, int n_in,
                              void* d_out, int out_size)
{
    const float* x      = (const float*)d_in[0];
    const int*   ei     = (const int*)d_in[1];   // int32 (JAX x64 disabled)
    const float* W1     = (const float*)d_in[2];
    const float* a_src1 = (const float*)d_in[3];
    const float* a_dst1 = (const float*)d_in[4];
    const float* b1     = (const float*)d_in[5];
    const float* W2     = (const float*)d_in[6];
    const float* a_src2 = (const float*)d_in[7];
    const float* a_dst2 = (const float*)d_in[8];
    const float* b2     = (const float*)d_in[9];
    float*       out    = (float*)d_out;

    const int n = in_sizes[0] / IND;      // 50000
    const int E = in_sizes[1] / 2;        // 800000
    const int tot = E + n;

    const int nb256 = (n + 255) / 256;
    const int eb256 = (tot + 255) / 256;
    const int nscan = (n + 1023) / 1024;

    // 0: fused bf16 splits
    {
        const int nx4 = (n * IND) / 4;
        const int tot4 = nx4 + IND * D1 / 4 + D1 * D2 / 4;
        split_all_kernel<<<(tot4 + 255) / 256, 256>>>(x, W1, W2, nx4);
    }
    // 1: zero deg + alpha accumulators
    zero_all_kernel<<<(n * NHEADS + 255) / 256, 256>>>(n);
    // 2: histogram
    hist_kernel<<<eb256, 256>>>(ei, E, n);
    // 3: GEMM1 (+ fused alpha1)  <- ncu captures this index
    {
        dim3 grid(D1 / 64, (n + 127) / 128);
        mma_gemm_kernel<1><<<grid, 256>>>(n, a_src1, a_dst1);
    }
    // 4-7: scan + scatter
    scan1_kernel<<<nscan, 1024>>>(n);
    scan2_kernel<<<1, 64>>>(nscan, n);
    scan3_kernel<<<nb256, 256>>>(n);
    scatter_kernel<<<eb256, 256>>>(ei, E, n);
    // 8: aggregation layer 1
    {
        const int grid = (n + AGG_WARPS - 1) / AGG_WARPS;
        agg_kernel<NHEADS, 8, true><<<grid, AGG_WARPS * 32>>>(b1, nullptr, n);
    }
    // 9: GEMM2 (+ fused alpha2)
    {
        dim3 grid(D2 / 64, (n + 127) / 128);
        mma_gemm_kernel<2><<<grid, 256>>>(n, a_src2, a_dst2);
    }
    // 10: aggregation layer 2 -> out
    {
        const int grid = (n + AGG_WARPS - 1) / AGG_WARPS;
        agg_kernel<1, 2, false><<<grid, AGG_WARPS * 32>>>(b2, out, n);
    }
}